// round 12
// baseline (speedup 1.0000x reference)
#include <cuda_runtime.h>
#include <cuda_bf16.h>
#include <cstdint>

#define N_ROWS 16384
#define OBS    1024
#define HID    2048
#define LAT    256
#define VOCAB  8192
#define HQ     4
#define LN_EPS 1e-5f

// ---------------- tiling ----------------
#define TILE_M 128
#define TILE_N 128
#define TILE_K 64
#define NSTAGE 3
#define STAGE_BYTES (TILE_M*128 + TILE_N*128)
#define SMEM_AUX 0
#define SMEM_STAGE0 1024
#define DYN_SMEM (SMEM_STAGE0 + NSTAGE*STAGE_BYTES)
#define A_STAGE_OFF(s) (SMEM_STAGE0 + (s)*STAGE_BYTES)
#define B_STAGE_OFF(s) (A_STAGE_OFF(s) + TILE_M*128)

enum { EPI_H = 0, EPI_LAT = 1, EPI_RELU = 3, EPI_MSE = 4 };

// ---------------- dist kernel layout (A-resident, 8 n-tiles per CTA) ----------------
#define DSLICES 8                   // n-slices; 64 n-tiles / 8 = 8 per CTA
#define DNT 8                       // n-tiles per CTA
#define DS_ENORM 0                  // 4 KB (1024 floats)
#define DS_A     4096               // 64 KB: 4 K-chunks x 16 KB
#define DS_B     (4096 + 65536)     // 2 stages x 16 KB
#define DK_SMEM  (4096 + 65536 + 32768)   // 102400

// ---------------- scratch ----------------
__device__ __align__(1024) __nv_bfloat16 g_xb[(size_t)N_ROWS * OBS];
__device__ __align__(1024) __nv_bfloat16 g_hb[(size_t)N_ROWS * HID];
__device__ __align__(1024) __nv_bfloat16 g_residb[(size_t)N_ROWS * LAT];
__device__ __align__(1024) __nv_bfloat16 g_csb[(size_t)N_ROWS * LAT];
__device__ __align__(1024) __nv_bfloat16 g_cbb[(size_t)HQ * VOCAB * LAT];
__device__ __align__(1024) __nv_bfloat16 g_w1t[(size_t)HID * OBS];
__device__ __align__(1024) __nv_bfloat16 g_w2t[(size_t)LAT * HID];
__device__ __align__(1024) __nv_bfloat16 g_dw1t[(size_t)HID * LAT];
__device__ __align__(1024) __nv_bfloat16 g_dw2t[(size_t)OBS * HID];
__device__ float g_resid[(size_t)N_ROWS * LAT];
__device__ float g_codesum[(size_t)N_ROWS * LAT];
__device__ float g_enorm[HQ * VOCAB];
__device__ unsigned long long g_argmin[HQ * N_ROWS];
__device__ float g_vq_partials[HQ * (N_ROWS / 8)];
#define RP_COUNT ((N_ROWS / TILE_M) * (OBS / TILE_N))
__device__ float g_recon_partials[RP_COUNT];

// ---------------- helpers ----------------
__device__ __forceinline__ uint32_t smem_u32(const void* p) {
    uint32_t a;
    asm("{ .reg .u64 t; cvta.to.shared.u64 t, %1; cvt.u32.u64 %0, t; }" : "=r"(a) : "l"(p));
    return a;
}
#define SWZ(o) ((o) ^ (((o) >> 3) & 0x70))
#define CP_ASYNC16(dst, src) \
    asm volatile("cp.async.cg.shared.global [%0], [%1], 16;" :: "r"((uint32_t)(dst)), "l"(src))
#define CP_COMMIT() asm volatile("cp.async.commit_group;" ::: "memory")

__device__ __forceinline__ void ldsm_x4(uint32_t addr, uint32_t& r0, uint32_t& r1,
                                        uint32_t& r2, uint32_t& r3) {
    asm volatile("ldmatrix.sync.aligned.m8n8.x4.shared.b16 {%0,%1,%2,%3}, [%4];"
                 : "=r"(r0), "=r"(r1), "=r"(r2), "=r"(r3) : "r"(addr));
}
__device__ __forceinline__ void mma_bf16(float* d, uint32_t a0, uint32_t a1,
                                         uint32_t a2, uint32_t a3,
                                         uint32_t b0, uint32_t b1) {
    asm volatile("mma.sync.aligned.m16n8k16.row.col.f32.bf16.bf16.f32 "
                 "{%0,%1,%2,%3}, {%4,%5,%6,%7}, {%8,%9}, {%0,%1,%2,%3};"
                 : "+f"(d[0]), "+f"(d[1]), "+f"(d[2]), "+f"(d[3])
                 : "r"(a0), "r"(a1), "r"(a2), "r"(a3), "r"(b0), "r"(b1));
}
__device__ __forceinline__ unsigned f2ord(float f) {
    unsigned u = __float_as_uint(f);
    return (u & 0x80000000u) ? ~u : (u | 0x80000000u);
}

// fill one generic pipeline stage
__device__ __forceinline__ void fill_stage(
    uint32_t smem_base, int s, const __nv_bfloat16* __restrict__ A,
    const __nv_bfloat16* __restrict__ B, int K, int m0, int n0, int chunk, int tid)
{
    const int kt = chunk * TILE_K;
    const uint32_t a_s = smem_base + A_STAGE_OFF(s);
    const uint32_t b_s = smem_base + B_STAGE_OFF(s);
#pragma unroll
    for (int i = 0; i < 4; i++) {
        const int c = tid + i * 256;
        const int row = c >> 3;
        const int o = (c & 7) * 16;
        CP_ASYNC16(a_s + SWZ(row * 128 + o),
                   (const char*)(A + (size_t)(m0 + row) * K + kt) + o);
    }
#pragma unroll
    for (int i = 0; i < 4; i++) {
        const int c = tid + i * 256;
        const int row = c >> 3;
        const int o = (c & 7) * 16;
        CP_ASYNC16(b_s + SWZ(row * 128 + o),
                   (const char*)(B + (size_t)(n0 + row) * K + kt) + o);
    }
}

// ---------------- bf16 mma.sync GEMM with fused epilogues (enc/dec) ----------------
template<int EPI>
__global__ void __launch_bounds__(256, 2) tc_gemm(
    const __nv_bfloat16* __restrict__ A, const __nv_bfloat16* __restrict__ B, int K,
    const float* __restrict__ aux_vec,
    float* __restrict__ out_f32,
    __nv_bfloat16* __restrict__ out_bf16,
    const float* __restrict__ xref,
    float* __restrict__ partials)
{
    extern __shared__ __align__(1024) char smem[];
    const uint32_t smem_base = smem_u32(smem);
    const int tid = threadIdx.x;
    const int lane = tid & 31, wid = tid >> 5;
    const int wm = wid >> 1, wn = wid & 1;
    const int m0 = blockIdx.y * TILE_M;
    const int n0 = blockIdx.x * TILE_N;
    const int Nn = gridDim.x * TILE_N;
    const int niter = K >> 6;

    float* aux = (float*)(smem + SMEM_AUX);
    if (tid < 128) aux[tid] = aux_vec[n0 + tid];

    float acc[2][8][4];
#pragma unroll
    for (int fi = 0; fi < 2; fi++)
#pragma unroll
        for (int nf = 0; nf < 8; nf++)
#pragma unroll
            for (int q = 0; q < 4; q++) acc[fi][nf][q] = 0.f;

    const int a_row_l = wm * 32 + (lane & 15);
    const int a_kb_l  = (lane >> 4) * 16;
    const int b_row_l = wn * 64 + (lane & 7) + ((lane >> 4) & 1) * 8;
    const int b_kb_l  = (lane & 8) ? 16 : 0;

    fill_stage(smem_base, 0, A, B, K, m0, n0, 0, tid); CP_COMMIT();
    fill_stage(smem_base, 1, A, B, K, m0, n0, 1, tid); CP_COMMIT();

    int s = 0;
    for (int it = 0; it < niter; ++it) {
        if (it < niter - 1) { asm volatile("cp.async.wait_group 1;" ::: "memory"); }
        else                { asm volatile("cp.async.wait_group 0;" ::: "memory"); }
        __syncthreads();

        if (it + 2 < niter) {
            int fs = s + 2; if (fs >= NSTAGE) fs -= NSTAGE;
            fill_stage(smem_base, fs, A, B, K, m0, n0, it + 2, tid);
            CP_COMMIT();
        }

        const uint32_t a_s = smem_base + A_STAGE_OFF(s);
        const uint32_t b_s = smem_base + B_STAGE_OFF(s);
#pragma unroll
        for (int k = 0; k < 4; ++k) {
            const int kb = k * 32;
            uint32_t a[2][4];
#pragma unroll
            for (int fi = 0; fi < 2; fi++) {
                const int row = a_row_l + fi * 16;
                ldsm_x4(a_s + SWZ(row * 128 + kb + a_kb_l),
                        a[fi][0], a[fi][1], a[fi][2], a[fi][3]);
            }
            uint32_t b[8][2];
#pragma unroll
            for (int nf2 = 0; nf2 < 4; nf2++) {
                const int row = b_row_l + nf2 * 16;
                ldsm_x4(b_s + SWZ(row * 128 + kb + b_kb_l),
                        b[nf2*2][0], b[nf2*2][1], b[nf2*2+1][0], b[nf2*2+1][1]);
            }
#pragma unroll
            for (int fi = 0; fi < 2; fi++)
#pragma unroll
                for (int nf = 0; nf < 8; nf++)
                    mma_bf16(acc[fi][nf], a[fi][0], a[fi][1], a[fi][2], a[fi][3],
                             b[nf][0], b[nf][1]);
        }
        if (++s >= NSTAGE) s = 0;
    }

    const int tr = lane >> 2;
    const int tc = (lane & 3) * 2;

    if (EPI == EPI_MSE) {
        float ls = 0.f;
#pragma unroll
        for (int fi = 0; fi < 2; fi++)
#pragma unroll
            for (int half = 0; half < 2; half++) {
                const size_t row = (size_t)(m0 + wm * 32 + fi * 16 + tr + half * 8);
#pragma unroll
                for (int nf = 0; nf < 8; nf++) {
                    const int col = wn * 64 + nf * 8 + tc;
                    const float2 xv = *(const float2*)&xref[row * OBS + n0 + col];
                    float e0 = acc[fi][nf][half*2+0] + aux[col]   - xv.x;
                    float e1 = acc[fi][nf][half*2+1] + aux[col+1] - xv.y;
                    ls = fmaf(e0, e0, ls);
                    ls = fmaf(e1, e1, ls);
                }
            }
        __syncthreads();
        float* red = (float*)(smem + SMEM_STAGE0);
        red[tid] = ls;
        __syncthreads();
#pragma unroll
        for (int st = 128; st > 0; st >>= 1) {
            if (tid < st) red[tid] += red[tid + st];
            __syncthreads();
        }
        if (tid == 0) partials[blockIdx.y * gridDim.x + blockIdx.x] = red[0];
    } else {
#pragma unroll
        for (int fi = 0; fi < 2; fi++)
#pragma unroll
            for (int half = 0; half < 2; half++) {
                const size_t row = (size_t)(m0 + wm * 32 + fi * 16 + tr + half * 8);
#pragma unroll
                for (int nf = 0; nf < 8; nf++) {
                    const int col = wn * 64 + nf * 8 + tc;
                    float v0 = acc[fi][nf][half*2+0] + aux[col];
                    float v1 = acc[fi][nf][half*2+1] + aux[col+1];
                    if (EPI == EPI_RELU) { v0 = fmaxf(v0, 0.f); v1 = fmaxf(v1, 0.f); }
                    if (EPI == EPI_LAT)
                        *(float2*)&out_f32[row * Nn + n0 + col] = make_float2(v0, v1);
                    __nv_bfloat162 p = __float22bfloat162_rn(make_float2(v0, v1));
                    *(__nv_bfloat162*)&out_bf16[row * Nn + n0 + col] = p;
                }
            }
    }
}

// ---------------- A-resident distance/argmin kernel ----------------
// grid (DSLICES, N_ROWS/128); each CTA: 128 rows resident, DNT n-tiles streamed.
__device__ __forceinline__ void dist_fill_b(
    uint32_t base, int stage, const __nv_bfloat16* __restrict__ B,
    int n0, int kc, int tid)
{
    const uint32_t b_s = base + DS_B + stage * 16384;
#pragma unroll
    for (int i = 0; i < 4; i++) {
        const int c = tid + i * 256;
        const int row = c >> 3;
        const int o = (c & 7) * 16;
        CP_ASYNC16(b_s + SWZ(row * 128 + o),
                   (const char*)(B + (size_t)(n0 + row) * 256) + kc * 128 + o);
    }
}

__global__ void __launch_bounds__(256, 2) dist_kernel(
    const __nv_bfloat16* __restrict__ A,   // resid bf16 [N_ROWS, 256]
    const __nv_bfloat16* __restrict__ B,   // codebook level bf16 [VOCAB, 256]
    const float* __restrict__ enorm,
    unsigned long long* __restrict__ argmin)
{
    extern __shared__ __align__(1024) char smem[];
    const uint32_t base = smem_u32(smem);
    const int tid = threadIdx.x;
    const int lane = tid & 31, wid = tid >> 5;
    const int wm = wid >> 1, wn = wid & 1;
    const int m0 = blockIdx.y * 128;
    const int nbase = blockIdx.x * (DNT * 128);

    // enorm slice (DNT*128 = 1024 floats)
    float* esm = (float*)(smem + DS_ENORM);
    ((float4*)esm)[tid] = ((const float4*)(enorm + nbase))[tid];

    // A resident: 4 K-chunks x [128 rows x 128B], each chunk swizzled independently
#pragma unroll
    for (int i = 0; i < 16; i++) {
        const int c = tid + i * 256;          // 0..4095 (16B units)
        const int chunk = c >> 10;
        const int u = c & 1023;
        const int row = u >> 3;
        const int o = (u & 7) * 16;
        CP_ASYNC16(base + DS_A + chunk * 16384 + SWZ(row * 128 + o),
                   (const char*)(A + (size_t)(m0 + row) * 256) + chunk * 128 + o);
    }
    CP_COMMIT();
    dist_fill_b(base, 0, B, nbase, 0, tid); CP_COMMIT();
    dist_fill_b(base, 1, B, nbase, 1, tid); CP_COMMIT();

    float acc[2][8][4];
#pragma unroll
    for (int fi = 0; fi < 2; fi++)
#pragma unroll
        for (int nf = 0; nf < 8; nf++)
#pragma unroll
            for (int q = 0; q < 4; q++) acc[fi][nf][q] = 0.f;

    float best[2][2];
    int bi[2][2];
#pragma unroll
    for (int fi = 0; fi < 2; fi++)
#pragma unroll
        for (int hf = 0; hf < 2; hf++) { best[fi][hf] = __int_as_float(0x7f800000); bi[fi][hf] = 0; }

    const int a_row_l = wm * 32 + (lane & 15);
    const int a_kb_l  = (lane >> 4) * 16;
    const int b_row_l = wn * 64 + (lane & 7) + ((lane >> 4) & 1) * 8;
    const int b_kb_l  = (lane & 8) ? 16 : 0;
    const int tc = (lane & 3) * 2;

    const int NIT = DNT * 4;
    for (int g = 0; g < NIT; ++g) {
        if (g < NIT - 1) { asm volatile("cp.async.wait_group 1;" ::: "memory"); }
        else             { asm volatile("cp.async.wait_group 0;" ::: "memory"); }
        __syncthreads();

        const int kc = g & 3;
        const uint32_t a_s = base + DS_A + kc * 16384;
        const uint32_t b_s = base + DS_B + (g & 1) * 16384;
#pragma unroll
        for (int k = 0; k < 4; ++k) {
            const int kb = k * 32;
            uint32_t a[2][4];
#pragma unroll
            for (int fi = 0; fi < 2; fi++) {
                const int row = a_row_l + fi * 16;
                ldsm_x4(a_s + SWZ(row * 128 + kb + a_kb_l),
                        a[fi][0], a[fi][1], a[fi][2], a[fi][3]);
            }
            uint32_t b[8][2];
#pragma unroll
            for (int nf2 = 0; nf2 < 4; nf2++) {
                const int row = b_row_l + nf2 * 16;
                ldsm_x4(b_s + SWZ(row * 128 + kb + b_kb_l),
                        b[nf2*2][0], b[nf2*2][1], b[nf2*2+1][0], b[nf2*2+1][1]);
            }
#pragma unroll
            for (int fi = 0; fi < 2; fi++)
#pragma unroll
                for (int nf = 0; nf < 8; nf++)
                    mma_bf16(acc[fi][nf], a[fi][0], a[fi][1], a[fi][2], a[fi][3],
                             b[nf][0], b[nf][1]);
        }

        if (kc == 3) {
            const int lt = (g >> 2) * 128;          // local col base within slice
#pragma unroll
            for (int fi = 0; fi < 2; fi++)
#pragma unroll
                for (int hf = 0; hf < 2; hf++) {
                    float bst = best[fi][hf];
                    int bidx = bi[fi][hf];
#pragma unroll
                    for (int nf = 0; nf < 8; nf++) {
                        const int lc = lt + wn * 64 + nf * 8 + tc;
                        const float d0 = fmaf(-2.f, acc[fi][nf][hf*2+0], esm[lc]);
                        const float d1 = fmaf(-2.f, acc[fi][nf][hf*2+1], esm[lc+1]);
                        if (d0 < bst) { bst = d0; bidx = nbase + lc; }
                        if (d1 < bst) { bst = d1; bidx = nbase + lc + 1; }
                    }
                    best[fi][hf] = bst;
                    bi[fi][hf] = bidx;
                }
#pragma unroll
            for (int fi = 0; fi < 2; fi++)
#pragma unroll
                for (int nf = 0; nf < 8; nf++)
#pragma unroll
                    for (int q = 0; q < 4; q++) acc[fi][nf][q] = 0.f;
        }

        __syncthreads();     // all warps done reading stage (g&1) before refill
        if (g + 2 < NIT) {
            const int gn = g + 2;
            dist_fill_b(base, g & 1, B, nbase + (gn >> 2) * 128, gn & 3, tid);
            CP_COMMIT();
        }
    }

    // final: quad-reduce and one atomicMin per row
    const int tr = lane >> 2;
#pragma unroll
    for (int fi = 0; fi < 2; fi++)
#pragma unroll
        for (int hf = 0; hf < 2; hf++) {
            unsigned long long key =
                ((unsigned long long)f2ord(best[fi][hf]) << 32) | (unsigned)bi[fi][hf];
            unsigned long long o;
            o = __shfl_xor_sync(0xffffffffu, key, 1); if (o < key) key = o;
            o = __shfl_xor_sync(0xffffffffu, key, 2); if (o < key) key = o;
            if ((lane & 3) == 0) {
                const int row = m0 + wm * 32 + fi * 16 + tr + hf * 8;
                atomicMin(&argmin[row], key);
            }
        }
}

// ---------------- fused prep: x->bf16, cb->bf16+enorm, argmin init, transposes ----------------
#define PREP_XB   16384
#define PREP_CB   4096
#define PREP_ARG  256
#define PREP_TR1  2048
#define PREP_TR2  512
#define PREP_TR3  512
#define PREP_TR4  2048
#define PREP_GRID (PREP_XB + PREP_CB + PREP_ARG + PREP_TR1 + PREP_TR2 + PREP_TR3 + PREP_TR4)

__global__ void __launch_bounds__(256) prep_kernel(
    const float* __restrict__ x, const float* __restrict__ cb,
    const float* __restrict__ ew1, const float* __restrict__ ew2,
    const float* __restrict__ dw1, const float* __restrict__ dw2,
    __nv_bfloat16* __restrict__ xb, __nv_bfloat16* __restrict__ cbb,
    float* __restrict__ en, unsigned long long* __restrict__ arg,
    __nv_bfloat16* __restrict__ w1t, __nv_bfloat16* __restrict__ w2t,
    __nv_bfloat16* __restrict__ dw1t, __nv_bfloat16* __restrict__ dw2t)
{
    __shared__ float tsm[32][33];
    const int b = blockIdx.x;
    const int tid = threadIdx.x;
    if (b < PREP_XB) {
        const size_t i = (size_t)b * 256 + tid;
        const float4 v = ((const float4*)x)[i];
        ((__nv_bfloat162*)xb)[2 * i + 0] = __float22bfloat162_rn(make_float2(v.x, v.y));
        ((__nv_bfloat162*)xb)[2 * i + 1] = __float22bfloat162_rn(make_float2(v.z, v.w));
    } else if (b < PREP_XB + PREP_CB) {
        const int row = (b - PREP_XB) * 8 + (tid >> 5);
        const int lane = tid & 31;
        float s = 0.f;
#pragma unroll
        for (int h = 0; h < 2; h++) {
            const float4 v = ((const float4*)cb)[(size_t)row * 64 + h * 32 + lane];
            s = fmaf(v.x, v.x, s); s = fmaf(v.y, v.y, s);
            s = fmaf(v.z, v.z, s); s = fmaf(v.w, v.w, s);
            uint2 p;
            __nv_bfloat162 p0 = __float22bfloat162_rn(make_float2(v.x, v.y));
            __nv_bfloat162 p1 = __float22bfloat162_rn(make_float2(v.z, v.w));
            p.x = *(uint32_t*)&p0; p.y = *(uint32_t*)&p1;
            ((uint2*)cbb)[(size_t)row * 64 + h * 32 + lane] = p;
        }
#pragma unroll
        for (int off = 16; off > 0; off >>= 1) s += __shfl_down_sync(0xffffffffu, s, off);
        if (lane == 0) en[row] = s;
    } else if (b < PREP_XB + PREP_CB + PREP_ARG) {
        const int ab = b - PREP_XB - PREP_CB;
        arg[(size_t)ab * 256 + tid] = ~0ull;
    } else {
        int t = b - PREP_XB - PREP_CB - PREP_ARG;
        const float* in; __nv_bfloat16* outp; int R, C;
        if (t < PREP_TR1)                 { in = ew1; outp = w1t;  R = OBS; C = HID; }
        else if (t < PREP_TR1 + PREP_TR2) { t -= PREP_TR1; in = ew2; outp = w2t;  R = HID; C = LAT; }
        else if (t < PREP_TR1 + PREP_TR2 + PREP_TR3)
                                          { t -= PREP_TR1 + PREP_TR2; in = dw1; outp = dw1t; R = LAT; C = HID; }
        else                              { t -= PREP_TR1 + PREP_TR2 + PREP_TR3; in = dw2; outp = dw2t; R = HID; C = OBS; }
        const int cw = C / 32;
        const int c0 = (t % cw) * 32, r0 = (t / cw) * 32;
        const int tx = tid & 31, ty = tid >> 5;
#pragma unroll
        for (int i = 0; i < 32; i += 8)
            tsm[ty + i][tx] = in[(size_t)(r0 + ty + i) * C + c0 + tx];
        __syncthreads();
#pragma unroll
        for (int i = 0; i < 32; i += 8)
            outp[(size_t)(c0 + ty + i) * R + r0 + tx] = __float2bfloat16_rn(tsm[tx][ty + i]);
    }
}

// ---------------- LayerNorm + ReLU on bf16 in place (uint4 I/O) ----------------
__global__ void __launch_bounds__(256) ln_relu_kernel(
    __nv_bfloat16* __restrict__ h, const float* __restrict__ g, const float* __restrict__ b)
{
    const int row = blockIdx.x;
    uint4* hr = (uint4*)(h + (size_t)row * HID);
    const uint4 v = hr[threadIdx.x];
    float f[8];
    {
        const __nv_bfloat162* p = (const __nv_bfloat162*)&v;
#pragma unroll
        for (int i = 0; i < 4; i++) {
            f[2 * i]     = __bfloat162float(p[i].x);
            f[2 * i + 1] = __bfloat162float(p[i].y);
        }
    }
    float s = 0.f, s2 = 0.f;
#pragma unroll
    for (int i = 0; i < 8; i++) { s += f[i]; s2 = fmaf(f[i], f[i], s2); }

    __shared__ float sh1[256], sh2[256];
    sh1[threadIdx.x] = s; sh2[threadIdx.x] = s2;
    __syncthreads();
    for (int st = 128; st > 0; st >>= 1) {
        if (threadIdx.x < st) {
            sh1[threadIdx.x] += sh1[threadIdx.x + st];
            sh2[threadIdx.x] += sh2[threadIdx.x + st];
        }
        __syncthreads();
    }
    const float mu  = sh1[0] * (1.f / HID);
    const float var = sh2[0] * (1.f / HID) - mu * mu;
    const float inv = rsqrtf(var + LN_EPS);

    const float4 g0 = ((const float4*)g)[threadIdx.x * 2];
    const float4 g1 = ((const float4*)g)[threadIdx.x * 2 + 1];
    const float4 b0 = ((const float4*)b)[threadIdx.x * 2];
    const float4 b1 = ((const float4*)b)[threadIdx.x * 2 + 1];
    const float gg[8] = {g0.x, g0.y, g0.z, g0.w, g1.x, g1.y, g1.z, g1.w};
    const float bb[8] = {b0.x, b0.y, b0.z, b0.w, b1.x, b1.y, b1.z, b1.w};

    uint4 o;
    __nv_bfloat162* po = (__nv_bfloat162*)&o;
#pragma unroll
    for (int i = 0; i < 4; i++) {
        const float v0 = fmaxf((f[2*i]   - mu) * inv * gg[2*i]   + bb[2*i],   0.f);
        const float v1 = fmaxf((f[2*i+1] - mu) * inv * gg[2*i+1] + bb[2*i+1], 0.f);
        po[i] = __float22bfloat162_rn(make_float2(v0, v1));
    }
    hr[threadIdx.x] = o;
}

// ---------------- VQ gather + loss partial + resid/codesum update ----------------
template<bool FIRST, bool LAST>
__global__ void __launch_bounds__(256) vq_gather_kernel(
    const float* __restrict__ E, float* __restrict__ resid,
    __nv_bfloat16* __restrict__ residb,
    float* __restrict__ codesum, __nv_bfloat16* __restrict__ csb,
    const unsigned long long* __restrict__ argmin, float* __restrict__ partials)
{
    const int warp = threadIdx.x >> 5;
    const int lane = threadIdx.x & 31;
    const int row  = blockIdx.x * 8 + warp;
    const unsigned idx = (unsigned)(argmin[row] & 0xffffffffu);
    const float* q = E + (size_t)idx * LAT;
    float* rr = resid   + (size_t)row * LAT;
    float* cs = codesum + (size_t)row * LAT;
    __nv_bfloat16* rb = residb + (size_t)row * LAT;
    __nv_bfloat16* cbp = csb   + (size_t)row * LAT;
    float lsum = 0.f;
#pragma unroll
    for (int c = lane * 4; c < LAT; c += 128) {
        const float4 qv = *(const float4*)&q[c];
        const float4 rv = *(const float4*)&rr[c];
        const float dx = qv.x - rv.x, dy = qv.y - rv.y;
        const float dz = qv.z - rv.z, dw = qv.w - rv.w;
        lsum += dx * dx + dy * dy + dz * dz + dw * dw;
        const float4 nr = make_float4(rv.x - qv.x, rv.y - qv.y, rv.z - qv.z, rv.w - qv.w);
        *(float4*)&rr[c] = nr;
        float4 cv;
        if (FIRST) cv = qv;
        else {
            cv = *(float4*)&cs[c];
            cv.x += qv.x; cv.y += qv.y; cv.z += qv.z; cv.w += qv.w;
        }
        *(float4*)&cs[c] = cv;
        if (LAST) {
            ((__nv_bfloat162*)&cbp[c])[0] = __float22bfloat162_rn(make_float2(cv.x, cv.y));
            ((__nv_bfloat162*)&cbp[c])[1] = __float22bfloat162_rn(make_float2(cv.z, cv.w));
        } else {
            ((__nv_bfloat162*)&rb[c])[0] = __float22bfloat162_rn(make_float2(nr.x, nr.y));
            ((__nv_bfloat162*)&rb[c])[1] = __float22bfloat162_rn(make_float2(nr.z, nr.w));
        }
    }
#pragma unroll
    for (int off = 16; off > 0; off >>= 1) lsum += __shfl_down_sync(0xffffffffu, lsum, off);
    __shared__ float ws[8];
    if (lane == 0) ws[warp] = lsum;
    __syncthreads();
    if (threadIdx.x == 0) {
        float t = 0.f;
#pragma unroll
        for (int w = 0; w < 8; w++) t += ws[w];
        partials[blockIdx.x] = t;
    }
}

// ---------------- final deterministic reduction ----------------
__global__ void __launch_bounds__(256) final_kernel(
    const float* __restrict__ vqp, const float* __restrict__ rp, float* __restrict__ out)
{
    __shared__ float sv[256], sr[256];
    float a = 0.f, b = 0.f;
    for (int i = threadIdx.x; i < HQ * (N_ROWS / 8); i += 256) a += vqp[i];
    for (int i = threadIdx.x; i < RP_COUNT; i += 256) b += rp[i];
    sv[threadIdx.x] = a; sr[threadIdx.x] = b;
    __syncthreads();
    for (int s = 128; s > 0; s >>= 1) {
        if (threadIdx.x < s) {
            sv[threadIdx.x] += sv[threadIdx.x + s];
            sr[threadIdx.x] += sr[threadIdx.x + s];
        }
        __syncthreads();
    }
    if (threadIdx.x == 0) {
        out[0] = 1.5f * sv[0] / ((float)N_ROWS * (float)LAT)
               + 0.5f * sr[0] / ((float)N_ROWS * (float)OBS);
    }
}

// ---------------- host launcher ----------------
extern "C" void kernel_launch(void* const* d_in, const int* in_sizes, int n_in,
                              void* d_out, int out_size)
{
    const float* x   = (const float*)d_in[0];
    const float* cb  = (const float*)d_in[1];
    const float* ew1 = (const float*)d_in[2];
    const float* eb1 = (const float*)d_in[3];
    const float* lng = (const float*)d_in[4];
    const float* lnb = (const float*)d_in[5];
    const float* ew2 = (const float*)d_in[6];
    const float* eb2 = (const float*)d_in[7];
    const float* dw1 = (const float*)d_in[8];
    const float* db1 = (const float*)d_in[9];
    const float* dw2 = (const float*)d_in[10];
    const float* db2 = (const float*)d_in[11];
    float* out = (float*)d_out;

    float *p_resid, *p_codesum, *p_enorm, *p_vqp, *p_rp;
    unsigned long long* p_arg;
    __nv_bfloat16 *p_xb, *p_hb, *p_residb, *p_csb, *p_cbb, *p_w1t, *p_w2t, *p_dw1t, *p_dw2t;
    cudaGetSymbolAddress((void**)&p_resid,   g_resid);
    cudaGetSymbolAddress((void**)&p_codesum, g_codesum);
    cudaGetSymbolAddress((void**)&p_enorm,   g_enorm);
    cudaGetSymbolAddress((void**)&p_arg,     g_argmin);
    cudaGetSymbolAddress((void**)&p_vqp,     g_vq_partials);
    cudaGetSymbolAddress((void**)&p_rp,      g_recon_partials);
    cudaGetSymbolAddress((void**)&p_xb,      g_xb);
    cudaGetSymbolAddress((void**)&p_hb,      g_hb);
    cudaGetSymbolAddress((void**)&p_residb,  g_residb);
    cudaGetSymbolAddress((void**)&p_csb,     g_csb);
    cudaGetSymbolAddress((void**)&p_cbb,     g_cbb);
    cudaGetSymbolAddress((void**)&p_w1t,     g_w1t);
    cudaGetSymbolAddress((void**)&p_w2t,     g_w2t);
    cudaGetSymbolAddress((void**)&p_dw1t,    g_dw1t);
    cudaGetSymbolAddress((void**)&p_dw2t,    g_dw2t);

    cudaFuncSetAttribute(tc_gemm<EPI_H>,    cudaFuncAttributeMaxDynamicSharedMemorySize, DYN_SMEM);
    cudaFuncSetAttribute(tc_gemm<EPI_LAT>,  cudaFuncAttributeMaxDynamicSharedMemorySize, DYN_SMEM);
    cudaFuncSetAttribute(tc_gemm<EPI_RELU>, cudaFuncAttributeMaxDynamicSharedMemorySize, DYN_SMEM);
    cudaFuncSetAttribute(tc_gemm<EPI_MSE>,  cudaFuncAttributeMaxDynamicSharedMemorySize, DYN_SMEM);
    cudaFuncSetAttribute(dist_kernel,       cudaFuncAttributeMaxDynamicSharedMemorySize, DK_SMEM);

    // 1: fused prep (x->bf16, cb->bf16+enorm, argmin init, all transposes)
    prep_kernel<<<PREP_GRID, 256>>>(x, cb, ew1, ew2, dw1, dw2,
                                    p_xb, p_cbb, p_enorm, p_arg,
                                    p_w1t, p_w2t, p_dw1t, p_dw2t);
    // 2: encoder GEMM1 -> bf16 h
    tc_gemm<EPI_H><<<dim3(HID / TILE_N, N_ROWS / TILE_M), 256, DYN_SMEM>>>(
        p_xb, p_w1t, OBS, eb1, nullptr, p_hb, nullptr, nullptr);
    // 3: LN+ReLU in place on bf16
    ln_relu_kernel<<<N_ROWS, 256>>>(p_hb, lng, lnb);
    // 4: encoder GEMM2 -> resid f32 + bf16
    tc_gemm<EPI_LAT><<<dim3(LAT / TILE_N, N_ROWS / TILE_M), 256, DYN_SMEM>>>(
        p_hb, p_w2t, HID, eb2, p_resid, p_residb, nullptr, nullptr);

    // residual VQ levels (A-resident dist kernel, 8 n-tiles per CTA)
    for (int l = 0; l < HQ; ++l) {
        dist_kernel<<<dim3(DSLICES, N_ROWS / 128), 256, DK_SMEM>>>(
            p_residb, p_cbb + (size_t)l * VOCAB * LAT,
            p_enorm + l * VOCAB, p_arg + l * N_ROWS);
        const float* El = cb + (size_t)l * VOCAB * LAT;
        float* vp = p_vqp + l * (N_ROWS / 8);
        if (l == 0)
            vq_gather_kernel<true, false><<<N_ROWS / 8, 256>>>(
                El, p_resid, p_residb, p_codesum, p_csb, p_arg + l * N_ROWS, vp);
        else if (l == HQ - 1)
            vq_gather_kernel<false, true><<<N_ROWS / 8, 256>>>(
                El, p_resid, p_residb, p_codesum, p_csb, p_arg + l * N_ROWS, vp);
        else
            vq_gather_kernel<false, false><<<N_ROWS / 8, 256>>>(
                El, p_resid, p_residb, p_codesum, p_csb, p_arg + l * N_ROWS, vp);
    }

    // decoder (g_hb reused as dh bf16)
    tc_gemm<EPI_RELU><<<dim3(HID / TILE_N, N_ROWS / TILE_M), 256, DYN_SMEM>>>(
        p_csb, p_dw1t, LAT, db1, nullptr, p_hb, nullptr, nullptr);
    tc_gemm<EPI_MSE><<<dim3(OBS / TILE_N, N_ROWS / TILE_M), 256, DYN_SMEM>>>(
        p_hb, p_dw2t, HID, db2, nullptr, nullptr, x, p_rp);

    final_kernel<<<1, 256>>>(p_vqp, p_rp, out);
}

// round 13
// speedup vs baseline: 1.0055x; 1.0055x over previous
#include <cuda_runtime.h>
#include <cuda_bf16.h>
#include <cstdint>

#define N_ROWS 16384
#define OBS    1024
#define HID    2048
#define LAT    256
#define VOCAB  8192
#define HQ     4
#define LN_EPS 1e-5f

// ---------------- tiling ----------------
#define TILE_M 128
#define TILE_N 128
#define TILE_K 64
#define NSTAGE 3
#define STAGE_BYTES (TILE_M*128 + TILE_N*128)
#define SMEM_AUX 0
#define SMEM_STAGE0 1024
#define DYN_SMEM (SMEM_STAGE0 + NSTAGE*STAGE_BYTES)
#define A_STAGE_OFF(s) (SMEM_STAGE0 + (s)*STAGE_BYTES)
#define B_STAGE_OFF(s) (A_STAGE_OFF(s) + TILE_M*128)

enum { EPI_H = 0, EPI_LAT = 1, EPI_RELU = 3, EPI_MSE = 4 };

// ---------------- dist kernel layout (A-resident, 4 n-tiles per CTA) ----------------
#define DSLICES 16                  // n-slices; 64 n-tiles / 16 = 4 per CTA
#define DNT 4                       // n-tiles per CTA
#define DS_ENORM 0                  // 2 KB (512 floats)
#define DS_A     2048               // 64 KB: 4 K-chunks x 16 KB
#define DS_B     (2048 + 65536)     // 2 stages x 16 KB
#define DK_SMEM  (2048 + 65536 + 32768)   // 100352

// ---------------- scratch ----------------
__device__ __align__(1024) __nv_bfloat16 g_xb[(size_t)N_ROWS * OBS];
__device__ __align__(1024) __nv_bfloat16 g_hb[(size_t)N_ROWS * HID];
__device__ __align__(1024) __nv_bfloat16 g_residb[(size_t)N_ROWS * LAT];
__device__ __align__(1024) __nv_bfloat16 g_csb[(size_t)N_ROWS * LAT];
__device__ __align__(1024) __nv_bfloat16 g_cbb[(size_t)HQ * VOCAB * LAT];
__device__ __align__(1024) __nv_bfloat16 g_w1t[(size_t)HID * OBS];
__device__ __align__(1024) __nv_bfloat16 g_w2t[(size_t)LAT * HID];
__device__ __align__(1024) __nv_bfloat16 g_dw1t[(size_t)HID * LAT];
__device__ __align__(1024) __nv_bfloat16 g_dw2t[(size_t)OBS * HID];
__device__ float g_resid[(size_t)N_ROWS * LAT];
__device__ float g_codesum[(size_t)N_ROWS * LAT];
__device__ float g_enorm[HQ * VOCAB];
__device__ unsigned long long g_argmin[HQ * N_ROWS];
__device__ float g_vq_partials[HQ * (N_ROWS / 8)];
#define RP_COUNT ((N_ROWS / TILE_M) * (OBS / TILE_N))
__device__ float g_recon_partials[RP_COUNT];

// ---------------- helpers ----------------
__device__ __forceinline__ uint32_t smem_u32(const void* p) {
    uint32_t a;
    asm("{ .reg .u64 t; cvta.to.shared.u64 t, %1; cvt.u32.u64 %0, t; }" : "=r"(a) : "l"(p));
    return a;
}
#define SWZ(o) ((o) ^ (((o) >> 3) & 0x70))
#define CP_ASYNC16(dst, src) \
    asm volatile("cp.async.cg.shared.global [%0], [%1], 16;" :: "r"((uint32_t)(dst)), "l"(src))
#define CP_COMMIT() asm volatile("cp.async.commit_group;" ::: "memory")

__device__ __forceinline__ void ldsm_x4(uint32_t addr, uint32_t& r0, uint32_t& r1,
                                        uint32_t& r2, uint32_t& r3) {
    asm volatile("ldmatrix.sync.aligned.m8n8.x4.shared.b16 {%0,%1,%2,%3}, [%4];"
                 : "=r"(r0), "=r"(r1), "=r"(r2), "=r"(r3) : "r"(addr));
}
__device__ __forceinline__ void mma_bf16(float* d, uint32_t a0, uint32_t a1,
                                         uint32_t a2, uint32_t a3,
                                         uint32_t b0, uint32_t b1) {
    asm volatile("mma.sync.aligned.m16n8k16.row.col.f32.bf16.bf16.f32 "
                 "{%0,%1,%2,%3}, {%4,%5,%6,%7}, {%8,%9}, {%0,%1,%2,%3};"
                 : "+f"(d[0]), "+f"(d[1]), "+f"(d[2]), "+f"(d[3])
                 : "r"(a0), "r"(a1), "r"(a2), "r"(a3), "r"(b0), "r"(b1));
}
__device__ __forceinline__ unsigned f2ord(float f) {
    unsigned u = __float_as_uint(f);
    return (u & 0x80000000u) ? ~u : (u | 0x80000000u);
}

// fill one generic pipeline stage
__device__ __forceinline__ void fill_stage(
    uint32_t smem_base, int s, const __nv_bfloat16* __restrict__ A,
    const __nv_bfloat16* __restrict__ B, int K, int m0, int n0, int chunk, int tid)
{
    const int kt = chunk * TILE_K;
    const uint32_t a_s = smem_base + A_STAGE_OFF(s);
    const uint32_t b_s = smem_base + B_STAGE_OFF(s);
#pragma unroll
    for (int i = 0; i < 4; i++) {
        const int c = tid + i * 256;
        const int row = c >> 3;
        const int o = (c & 7) * 16;
        CP_ASYNC16(a_s + SWZ(row * 128 + o),
                   (const char*)(A + (size_t)(m0 + row) * K + kt) + o);
    }
#pragma unroll
    for (int i = 0; i < 4; i++) {
        const int c = tid + i * 256;
        const int row = c >> 3;
        const int o = (c & 7) * 16;
        CP_ASYNC16(b_s + SWZ(row * 128 + o),
                   (const char*)(B + (size_t)(n0 + row) * K + kt) + o);
    }
}

// ---------------- bf16 mma.sync GEMM with fused epilogues (enc/dec) ----------------
template<int EPI>
__global__ void __launch_bounds__(256, 2) tc_gemm(
    const __nv_bfloat16* __restrict__ A, const __nv_bfloat16* __restrict__ B, int K,
    const float* __restrict__ aux_vec,
    float* __restrict__ out_f32,
    __nv_bfloat16* __restrict__ out_bf16,
    const float* __restrict__ xref,
    float* __restrict__ partials)
{
    extern __shared__ __align__(1024) char smem[];
    const uint32_t smem_base = smem_u32(smem);
    const int tid = threadIdx.x;
    const int lane = tid & 31, wid = tid >> 5;
    const int wm = wid >> 1, wn = wid & 1;
    const int m0 = blockIdx.y * TILE_M;
    const int n0 = blockIdx.x * TILE_N;
    const int Nn = gridDim.x * TILE_N;
    const int niter = K >> 6;

    float* aux = (float*)(smem + SMEM_AUX);
    if (tid < 128) aux[tid] = aux_vec[n0 + tid];

    float acc[2][8][4];
#pragma unroll
    for (int fi = 0; fi < 2; fi++)
#pragma unroll
        for (int nf = 0; nf < 8; nf++)
#pragma unroll
            for (int q = 0; q < 4; q++) acc[fi][nf][q] = 0.f;

    const int a_row_l = wm * 32 + (lane & 15);
    const int a_kb_l  = (lane >> 4) * 16;
    const int b_row_l = wn * 64 + (lane & 7) + ((lane >> 4) & 1) * 8;
    const int b_kb_l  = (lane & 8) ? 16 : 0;

    fill_stage(smem_base, 0, A, B, K, m0, n0, 0, tid); CP_COMMIT();
    fill_stage(smem_base, 1, A, B, K, m0, n0, 1, tid); CP_COMMIT();

    int s = 0;
    for (int it = 0; it < niter; ++it) {
        if (it < niter - 1) { asm volatile("cp.async.wait_group 1;" ::: "memory"); }
        else                { asm volatile("cp.async.wait_group 0;" ::: "memory"); }
        __syncthreads();

        if (it + 2 < niter) {
            int fs = s + 2; if (fs >= NSTAGE) fs -= NSTAGE;
            fill_stage(smem_base, fs, A, B, K, m0, n0, it + 2, tid);
            CP_COMMIT();
        }

        const uint32_t a_s = smem_base + A_STAGE_OFF(s);
        const uint32_t b_s = smem_base + B_STAGE_OFF(s);
#pragma unroll
        for (int k = 0; k < 4; ++k) {
            const int kb = k * 32;
            uint32_t a[2][4];
#pragma unroll
            for (int fi = 0; fi < 2; fi++) {
                const int row = a_row_l + fi * 16;
                ldsm_x4(a_s + SWZ(row * 128 + kb + a_kb_l),
                        a[fi][0], a[fi][1], a[fi][2], a[fi][3]);
            }
            uint32_t b[8][2];
#pragma unroll
            for (int nf2 = 0; nf2 < 4; nf2++) {
                const int row = b_row_l + nf2 * 16;
                ldsm_x4(b_s + SWZ(row * 128 + kb + b_kb_l),
                        b[nf2*2][0], b[nf2*2][1], b[nf2*2+1][0], b[nf2*2+1][1]);
            }
#pragma unroll
            for (int fi = 0; fi < 2; fi++)
#pragma unroll
                for (int nf = 0; nf < 8; nf++)
                    mma_bf16(acc[fi][nf], a[fi][0], a[fi][1], a[fi][2], a[fi][3],
                             b[nf][0], b[nf][1]);
        }
        if (++s >= NSTAGE) s = 0;
    }

    const int tr = lane >> 2;
    const int tc = (lane & 3) * 2;

    if (EPI == EPI_MSE) {
        float ls = 0.f;
#pragma unroll
        for (int fi = 0; fi < 2; fi++)
#pragma unroll
            for (int half = 0; half < 2; half++) {
                const size_t row = (size_t)(m0 + wm * 32 + fi * 16 + tr + half * 8);
#pragma unroll
                for (int nf = 0; nf < 8; nf++) {
                    const int col = wn * 64 + nf * 8 + tc;
                    const float2 xv = *(const float2*)&xref[row * OBS + n0 + col];
                    float e0 = acc[fi][nf][half*2+0] + aux[col]   - xv.x;
                    float e1 = acc[fi][nf][half*2+1] + aux[col+1] - xv.y;
                    ls = fmaf(e0, e0, ls);
                    ls = fmaf(e1, e1, ls);
                }
            }
        __syncthreads();
        float* red = (float*)(smem + SMEM_STAGE0);
        red[tid] = ls;
        __syncthreads();
#pragma unroll
        for (int st = 128; st > 0; st >>= 1) {
            if (tid < st) red[tid] += red[tid + st];
            __syncthreads();
        }
        if (tid == 0) partials[blockIdx.y * gridDim.x + blockIdx.x] = red[0];
    } else {
#pragma unroll
        for (int fi = 0; fi < 2; fi++)
#pragma unroll
            for (int half = 0; half < 2; half++) {
                const size_t row = (size_t)(m0 + wm * 32 + fi * 16 + tr + half * 8);
#pragma unroll
                for (int nf = 0; nf < 8; nf++) {
                    const int col = wn * 64 + nf * 8 + tc;
                    float v0 = acc[fi][nf][half*2+0] + aux[col];
                    float v1 = acc[fi][nf][half*2+1] + aux[col+1];
                    if (EPI == EPI_RELU) { v0 = fmaxf(v0, 0.f); v1 = fmaxf(v1, 0.f); }
                    if (EPI == EPI_LAT)
                        *(float2*)&out_f32[row * Nn + n0 + col] = make_float2(v0, v1);
                    __nv_bfloat162 p = __float22bfloat162_rn(make_float2(v0, v1));
                    *(__nv_bfloat162*)&out_bf16[row * Nn + n0 + col] = p;
                }
            }
    }
}

// ---------------- A-resident distance/argmin kernel ----------------
// grid (DSLICES, N_ROWS/128); each CTA: 128 rows resident, DNT n-tiles streamed.
__device__ __forceinline__ void dist_fill_b(
    uint32_t base, int stage, const __nv_bfloat16* __restrict__ B,
    int n0, int kc, int tid)
{
    const uint32_t b_s = base + DS_B + stage * 16384;
#pragma unroll
    for (int i = 0; i < 4; i++) {
        const int c = tid + i * 256;
        const int row = c >> 3;
        const int o = (c & 7) * 16;
        CP_ASYNC16(b_s + SWZ(row * 128 + o),
                   (const char*)(B + (size_t)(n0 + row) * 256) + kc * 128 + o);
    }
}

__global__ void __launch_bounds__(256, 2) dist_kernel(
    const __nv_bfloat16* __restrict__ A,   // resid bf16 [N_ROWS, 256]
    const __nv_bfloat16* __restrict__ B,   // codebook level bf16 [VOCAB, 256]
    const float* __restrict__ enorm,
    unsigned long long* __restrict__ argmin)
{
    extern __shared__ __align__(1024) char smem[];
    const uint32_t base = smem_u32(smem);
    const int tid = threadIdx.x;
    const int lane = tid & 31, wid = tid >> 5;
    const int wm = wid >> 1, wn = wid & 1;
    const int m0 = blockIdx.y * 128;
    const int nbase = blockIdx.x * (DNT * 128);

    // enorm slice (DNT*128 = 512 floats)
    float* esm = (float*)(smem + DS_ENORM);
    if (tid < 128) ((float4*)esm)[tid] = ((const float4*)(enorm + nbase))[tid];

    // A resident: 4 K-chunks x [128 rows x 128B], each chunk swizzled independently
#pragma unroll
    for (int i = 0; i < 16; i++) {
        const int c = tid + i * 256;          // 0..4095 (16B units)
        const int chunk = c >> 10;
        const int u = c & 1023;
        const int row = u >> 3;
        const int o = (u & 7) * 16;
        CP_ASYNC16(base + DS_A + chunk * 16384 + SWZ(row * 128 + o),
                   (const char*)(A + (size_t)(m0 + row) * 256) + chunk * 128 + o);
    }
    CP_COMMIT();
    dist_fill_b(base, 0, B, nbase, 0, tid); CP_COMMIT();
    dist_fill_b(base, 1, B, nbase, 1, tid); CP_COMMIT();

    float acc[2][8][4];
#pragma unroll
    for (int fi = 0; fi < 2; fi++)
#pragma unroll
        for (int nf = 0; nf < 8; nf++)
#pragma unroll
            for (int q = 0; q < 4; q++) acc[fi][nf][q] = 0.f;

    float best[2][2];
    int bi[2][2];
#pragma unroll
    for (int fi = 0; fi < 2; fi++)
#pragma unroll
        for (int hf = 0; hf < 2; hf++) { best[fi][hf] = __int_as_float(0x7f800000); bi[fi][hf] = 0; }

    const int a_row_l = wm * 32 + (lane & 15);
    const int a_kb_l  = (lane >> 4) * 16;
    const int b_row_l = wn * 64 + (lane & 7) + ((lane >> 4) & 1) * 8;
    const int b_kb_l  = (lane & 8) ? 16 : 0;
    const int tc = (lane & 3) * 2;

    const int NIT = DNT * 4;
    for (int g = 0; g < NIT; ++g) {
        if (g < NIT - 1) { asm volatile("cp.async.wait_group 1;" ::: "memory"); }
        else             { asm volatile("cp.async.wait_group 0;" ::: "memory"); }
        __syncthreads();

        const int kc = g & 3;
        const uint32_t a_s = base + DS_A + kc * 16384;
        const uint32_t b_s = base + DS_B + (g & 1) * 16384;
#pragma unroll
        for (int k = 0; k < 4; ++k) {
            const int kb = k * 32;
            uint32_t a[2][4];
#pragma unroll
            for (int fi = 0; fi < 2; fi++) {
                const int row = a_row_l + fi * 16;
                ldsm_x4(a_s + SWZ(row * 128 + kb + a_kb_l),
                        a[fi][0], a[fi][1], a[fi][2], a[fi][3]);
            }
            uint32_t b[8][2];
#pragma unroll
            for (int nf2 = 0; nf2 < 4; nf2++) {
                const int row = b_row_l + nf2 * 16;
                ldsm_x4(b_s + SWZ(row * 128 + kb + b_kb_l),
                        b[nf2*2][0], b[nf2*2][1], b[nf2*2+1][0], b[nf2*2+1][1]);
            }
#pragma unroll
            for (int fi = 0; fi < 2; fi++)
#pragma unroll
                for (int nf = 0; nf < 8; nf++)
                    mma_bf16(acc[fi][nf], a[fi][0], a[fi][1], a[fi][2], a[fi][3],
                             b[nf][0], b[nf][1]);
        }

        __syncthreads();     // all warps done reading stage (g&1) before refill
        if (g + 2 < NIT) {
            const int gn = g + 2;
            dist_fill_b(base, g & 1, B, nbase + (gn >> 2) * 128, gn & 3, tid);
            CP_COMMIT();
        }

        if (kc == 3) {
            // n-tile complete: fold into running argmin (register/ro-smem only;
            // placed after fill issue so it overlaps in-flight cp.async)
            const int lt = (g >> 2) * 128;          // local col base within slice
#pragma unroll
            for (int fi = 0; fi < 2; fi++)
#pragma unroll
                for (int hf = 0; hf < 2; hf++) {
                    float bst = best[fi][hf];
                    int bidx = bi[fi][hf];
#pragma unroll
                    for (int nf = 0; nf < 8; nf++) {
                        const int lc = lt + wn * 64 + nf * 8 + tc;
                        const float d0 = fmaf(-2.f, acc[fi][nf][hf*2+0], esm[lc]);
                        const float d1 = fmaf(-2.f, acc[fi][nf][hf*2+1], esm[lc+1]);
                        if (d0 < bst) { bst = d0; bidx = nbase + lc; }
                        if (d1 < bst) { bst = d1; bidx = nbase + lc + 1; }
                    }
                    best[fi][hf] = bst;
                    bi[fi][hf] = bidx;
                }
#pragma unroll
            for (int fi = 0; fi < 2; fi++)
#pragma unroll
                for (int nf = 0; nf < 8; nf++)
#pragma unroll
                    for (int q = 0; q < 4; q++) acc[fi][nf][q] = 0.f;
        }
    }

    // final: quad-reduce and one atomicMin per row
    const int tr = lane >> 2;
#pragma unroll
    for (int fi = 0; fi < 2; fi++)
#pragma unroll
        for (int hf = 0; hf < 2; hf++) {
            unsigned long long key =
                ((unsigned long long)f2ord(best[fi][hf]) << 32) | (unsigned)bi[fi][hf];
            unsigned long long o;
            o = __shfl_xor_sync(0xffffffffu, key, 1); if (o < key) key = o;
            o = __shfl_xor_sync(0xffffffffu, key, 2); if (o < key) key = o;
            if ((lane & 3) == 0) {
                const int row = m0 + wm * 32 + fi * 16 + tr + hf * 8;
                atomicMin(&argmin[row], key);
            }
        }
}

// ---------------- fused prep: x->bf16, cb->bf16+enorm, argmin init, transposes ----------------
#define PREP_XB   16384
#define PREP_CB   4096
#define PREP_ARG  256
#define PREP_TR1  2048
#define PREP_TR2  512
#define PREP_TR3  512
#define PREP_TR4  2048
#define PREP_GRID (PREP_XB + PREP_CB + PREP_ARG + PREP_TR1 + PREP_TR2 + PREP_TR3 + PREP_TR4)

__global__ void __launch_bounds__(256) prep_kernel(
    const float* __restrict__ x, const float* __restrict__ cb,
    const float* __restrict__ ew1, const float* __restrict__ ew2,
    const float* __restrict__ dw1, const float* __restrict__ dw2,
    __nv_bfloat16* __restrict__ xb, __nv_bfloat16* __restrict__ cbb,
    float* __restrict__ en, unsigned long long* __restrict__ arg,
    __nv_bfloat16* __restrict__ w1t, __nv_bfloat16* __restrict__ w2t,
    __nv_bfloat16* __restrict__ dw1t, __nv_bfloat16* __restrict__ dw2t)
{
    __shared__ float tsm[32][33];
    const int b = blockIdx.x;
    const int tid = threadIdx.x;
    if (b < PREP_XB) {
        const size_t i = (size_t)b * 256 + tid;
        const float4 v = ((const float4*)x)[i];
        ((__nv_bfloat162*)xb)[2 * i + 0] = __float22bfloat162_rn(make_float2(v.x, v.y));
        ((__nv_bfloat162*)xb)[2 * i + 1] = __float22bfloat162_rn(make_float2(v.z, v.w));
    } else if (b < PREP_XB + PREP_CB) {
        const int row = (b - PREP_XB) * 8 + (tid >> 5);
        const int lane = tid & 31;
        float s = 0.f;
#pragma unroll
        for (int h = 0; h < 2; h++) {
            const float4 v = ((const float4*)cb)[(size_t)row * 64 + h * 32 + lane];
            s = fmaf(v.x, v.x, s); s = fmaf(v.y, v.y, s);
            s = fmaf(v.z, v.z, s); s = fmaf(v.w, v.w, s);
            uint2 p;
            __nv_bfloat162 p0 = __float22bfloat162_rn(make_float2(v.x, v.y));
            __nv_bfloat162 p1 = __float22bfloat162_rn(make_float2(v.z, v.w));
            p.x = *(uint32_t*)&p0; p.y = *(uint32_t*)&p1;
            ((uint2*)cbb)[(size_t)row * 64 + h * 32 + lane] = p;
        }
#pragma unroll
        for (int off = 16; off > 0; off >>= 1) s += __shfl_down_sync(0xffffffffu, s, off);
        if (lane == 0) en[row] = s;
    } else if (b < PREP_XB + PREP_CB + PREP_ARG) {
        const int ab = b - PREP_XB - PREP_CB;
        arg[(size_t)ab * 256 + tid] = ~0ull;
    } else {
        int t = b - PREP_XB - PREP_CB - PREP_ARG;
        const float* in; __nv_bfloat16* outp; int R, C;
        if (t < PREP_TR1)                 { in = ew1; outp = w1t;  R = OBS; C = HID; }
        else if (t < PREP_TR1 + PREP_TR2) { t -= PREP_TR1; in = ew2; outp = w2t;  R = HID; C = LAT; }
        else if (t < PREP_TR1 + PREP_TR2 + PREP_TR3)
                                          { t -= PREP_TR1 + PREP_TR2; in = dw1; outp = dw1t; R = LAT; C = HID; }
        else                              { t -= PREP_TR1 + PREP_TR2 + PREP_TR3; in = dw2; outp = dw2t; R = HID; C = OBS; }
        const int cw = C / 32;
        const int c0 = (t % cw) * 32, r0 = (t / cw) * 32;
        const int tx = tid & 31, ty = tid >> 5;
#pragma unroll
        for (int i = 0; i < 32; i += 8)
            tsm[ty + i][tx] = in[(size_t)(r0 + ty + i) * C + c0 + tx];
        __syncthreads();
#pragma unroll
        for (int i = 0; i < 32; i += 8)
            outp[(size_t)(c0 + ty + i) * R + r0 + tx] = __float2bfloat16_rn(tsm[tx][ty + i]);
    }
}

// ---------------- LayerNorm + ReLU on bf16 in place (uint4 I/O) ----------------
__global__ void __launch_bounds__(256) ln_relu_kernel(
    __nv_bfloat16* __restrict__ h, const float* __restrict__ g, const float* __restrict__ b)
{
    const int row = blockIdx.x;
    uint4* hr = (uint4*)(h + (size_t)row * HID);
    const uint4 v = hr[threadIdx.x];
    float f[8];
    {
        const __nv_bfloat162* p = (const __nv_bfloat162*)&v;
#pragma unroll
        for (int i = 0; i < 4; i++) {
            f[2 * i]     = __bfloat162float(p[i].x);
            f[2 * i + 1] = __bfloat162float(p[i].y);
        }
    }
    float s = 0.f, s2 = 0.f;
#pragma unroll
    for (int i = 0; i < 8; i++) { s += f[i]; s2 = fmaf(f[i], f[i], s2); }

    __shared__ float sh1[256], sh2[256];
    sh1[threadIdx.x] = s; sh2[threadIdx.x] = s2;
    __syncthreads();
    for (int st = 128; st > 0; st >>= 1) {
        if (threadIdx.x < st) {
            sh1[threadIdx.x] += sh1[threadIdx.x + st];
            sh2[threadIdx.x] += sh2[threadIdx.x + st];
        }
        __syncthreads();
    }
    const float mu  = sh1[0] * (1.f / HID);
    const float var = sh2[0] * (1.f / HID) - mu * mu;
    const float inv = rsqrtf(var + LN_EPS);

    const float4 g0 = ((const float4*)g)[threadIdx.x * 2];
    const float4 g1 = ((const float4*)g)[threadIdx.x * 2 + 1];
    const float4 b0 = ((const float4*)b)[threadIdx.x * 2];
    const float4 b1 = ((const float4*)b)[threadIdx.x * 2 + 1];
    const float gg[8] = {g0.x, g0.y, g0.z, g0.w, g1.x, g1.y, g1.z, g1.w};
    const float bb[8] = {b0.x, b0.y, b0.z, b0.w, b1.x, b1.y, b1.z, b1.w};

    uint4 o;
    __nv_bfloat162* po = (__nv_bfloat162*)&o;
#pragma unroll
    for (int i = 0; i < 4; i++) {
        const float v0 = fmaxf((f[2*i]   - mu) * inv * gg[2*i]   + bb[2*i],   0.f);
        const float v1 = fmaxf((f[2*i+1] - mu) * inv * gg[2*i+1] + bb[2*i+1], 0.f);
        po[i] = __float22bfloat162_rn(make_float2(v0, v1));
    }
    hr[threadIdx.x] = o;
}

// ---------------- VQ gather + loss partial + resid/codesum update ----------------
template<bool FIRST, bool LAST>
__global__ void __launch_bounds__(256) vq_gather_kernel(
    const float* __restrict__ E, float* __restrict__ resid,
    __nv_bfloat16* __restrict__ residb,
    float* __restrict__ codesum, __nv_bfloat16* __restrict__ csb,
    const unsigned long long* __restrict__ argmin, float* __restrict__ partials)
{
    const int warp = threadIdx.x >> 5;
    const int lane = threadIdx.x & 31;
    const int row  = blockIdx.x * 8 + warp;
    const unsigned idx = (unsigned)(argmin[row] & 0xffffffffu);
    const float* q = E + (size_t)idx * LAT;
    float* rr = resid   + (size_t)row * LAT;
    float* cs = codesum + (size_t)row * LAT;
    __nv_bfloat16* rb = residb + (size_t)row * LAT;
    __nv_bfloat16* cbp = csb   + (size_t)row * LAT;
    float lsum = 0.f;
#pragma unroll
    for (int c = lane * 4; c < LAT; c += 128) {
        const float4 qv = *(const float4*)&q[c];
        const float4 rv = *(const float4*)&rr[c];
        const float dx = qv.x - rv.x, dy = qv.y - rv.y;
        const float dz = qv.z - rv.z, dw = qv.w - rv.w;
        lsum += dx * dx + dy * dy + dz * dz + dw * dw;
        const float4 nr = make_float4(rv.x - qv.x, rv.y - qv.y, rv.z - qv.z, rv.w - qv.w);
        *(float4*)&rr[c] = nr;
        float4 cv;
        if (FIRST) cv = qv;
        else {
            cv = *(float4*)&cs[c];
            cv.x += qv.x; cv.y += qv.y; cv.z += qv.z; cv.w += qv.w;
        }
        *(float4*)&cs[c] = cv;
        if (LAST) {
            ((__nv_bfloat162*)&cbp[c])[0] = __float22bfloat162_rn(make_float2(cv.x, cv.y));
            ((__nv_bfloat162*)&cbp[c])[1] = __float22bfloat162_rn(make_float2(cv.z, cv.w));
        } else {
            ((__nv_bfloat162*)&rb[c])[0] = __float22bfloat162_rn(make_float2(nr.x, nr.y));
            ((__nv_bfloat162*)&rb[c])[1] = __float22bfloat162_rn(make_float2(nr.z, nr.w));
        }
    }
#pragma unroll
    for (int off = 16; off > 0; off >>= 1) lsum += __shfl_down_sync(0xffffffffu, lsum, off);
    __shared__ float ws[8];
    if (lane == 0) ws[warp] = lsum;
    __syncthreads();
    if (threadIdx.x == 0) {
        float t = 0.f;
#pragma unroll
        for (int w = 0; w < 8; w++) t += ws[w];
        partials[blockIdx.x] = t;
    }
}

// ---------------- final deterministic reduction ----------------
__global__ void __launch_bounds__(256) final_kernel(
    const float* __restrict__ vqp, const float* __restrict__ rp, float* __restrict__ out)
{
    __shared__ float sv[256], sr[256];
    float a = 0.f, b = 0.f;
    for (int i = threadIdx.x; i < HQ * (N_ROWS / 8); i += 256) a += vqp[i];
    for (int i = threadIdx.x; i < RP_COUNT; i += 256) b += rp[i];
    sv[threadIdx.x] = a; sr[threadIdx.x] = b;
    __syncthreads();
    for (int s = 128; s > 0; s >>= 1) {
        if (threadIdx.x < s) {
            sv[threadIdx.x] += sv[threadIdx.x + s];
            sr[threadIdx.x] += sr[threadIdx.x + s];
        }
        __syncthreads();
    }
    if (threadIdx.x == 0) {
        out[0] = 1.5f * sv[0] / ((float)N_ROWS * (float)LAT)
               + 0.5f * sr[0] / ((float)N_ROWS * (float)OBS);
    }
}

// ---------------- host launcher ----------------
extern "C" void kernel_launch(void* const* d_in, const int* in_sizes, int n_in,
                              void* d_out, int out_size)
{
    const float* x   = (const float*)d_in[0];
    const float* cb  = (const float*)d_in[1];
    const float* ew1 = (const float*)d_in[2];
    const float* eb1 = (const float*)d_in[3];
    const float* lng = (const float*)d_in[4];
    const float* lnb = (const float*)d_in[5];
    const float* ew2 = (const float*)d_in[6];
    const float* eb2 = (const float*)d_in[7];
    const float* dw1 = (const float*)d_in[8];
    const float* db1 = (const float*)d_in[9];
    const float* dw2 = (const float*)d_in[10];
    const float* db2 = (const float*)d_in[11];
    float* out = (float*)d_out;

    float *p_resid, *p_codesum, *p_enorm, *p_vqp, *p_rp;
    unsigned long long* p_arg;
    __nv_bfloat16 *p_xb, *p_hb, *p_residb, *p_csb, *p_cbb, *p_w1t, *p_w2t, *p_dw1t, *p_dw2t;
    cudaGetSymbolAddress((void**)&p_resid,   g_resid);
    cudaGetSymbolAddress((void**)&p_codesum, g_codesum);
    cudaGetSymbolAddress((void**)&p_enorm,   g_enorm);
    cudaGetSymbolAddress((void**)&p_arg,     g_argmin);
    cudaGetSymbolAddress((void**)&p_vqp,     g_vq_partials);
    cudaGetSymbolAddress((void**)&p_rp,      g_recon_partials);
    cudaGetSymbolAddress((void**)&p_xb,      g_xb);
    cudaGetSymbolAddress((void**)&p_hb,      g_hb);
    cudaGetSymbolAddress((void**)&p_residb,  g_residb);
    cudaGetSymbolAddress((void**)&p_csb,     g_csb);
    cudaGetSymbolAddress((void**)&p_cbb,     g_cbb);
    cudaGetSymbolAddress((void**)&p_w1t,     g_w1t);
    cudaGetSymbolAddress((void**)&p_w2t,     g_w2t);
    cudaGetSymbolAddress((void**)&p_dw1t,    g_dw1t);
    cudaGetSymbolAddress((void**)&p_dw2t,    g_dw2t);

    cudaFuncSetAttribute(tc_gemm<EPI_H>,    cudaFuncAttributeMaxDynamicSharedMemorySize, DYN_SMEM);
    cudaFuncSetAttribute(tc_gemm<EPI_LAT>,  cudaFuncAttributeMaxDynamicSharedMemorySize, DYN_SMEM);
    cudaFuncSetAttribute(tc_gemm<EPI_RELU>, cudaFuncAttributeMaxDynamicSharedMemorySize, DYN_SMEM);
    cudaFuncSetAttribute(tc_gemm<EPI_MSE>,  cudaFuncAttributeMaxDynamicSharedMemorySize, DYN_SMEM);
    cudaFuncSetAttribute(dist_kernel,       cudaFuncAttributeMaxDynamicSharedMemorySize, DK_SMEM);

    // 1: fused prep (x->bf16, cb->bf16+enorm, argmin init, all transposes)
    prep_kernel<<<PREP_GRID, 256>>>(x, cb, ew1, ew2, dw1, dw2,
                                    p_xb, p_cbb, p_enorm, p_arg,
                                    p_w1t, p_w2t, p_dw1t, p_dw2t);
    // 2: encoder GEMM1 -> bf16 h
    tc_gemm<EPI_H><<<dim3(HID / TILE_N, N_ROWS / TILE_M), 256, DYN_SMEM>>>(
        p_xb, p_w1t, OBS, eb1, nullptr, p_hb, nullptr, nullptr);
    // 3: LN+ReLU in place on bf16
    ln_relu_kernel<<<N_ROWS, 256>>>(p_hb, lng, lnb);
    // 4: encoder GEMM2 -> resid f32 + bf16
    tc_gemm<EPI_LAT><<<dim3(LAT / TILE_N, N_ROWS / TILE_M), 256, DYN_SMEM>>>(
        p_hb, p_w2t, HID, eb2, p_resid, p_residb, nullptr, nullptr);

    // residual VQ levels (A-resident dist kernel, 4 n-tiles per CTA)
    for (int l = 0; l < HQ; ++l) {
        dist_kernel<<<dim3(DSLICES, N_ROWS / 128), 256, DK_SMEM>>>(
            p_residb, p_cbb + (size_t)l * VOCAB * LAT,
            p_enorm + l * VOCAB, p_arg + l * N_ROWS);
        const float* El = cb + (size_t)l * VOCAB * LAT;
        float* vp = p_vqp + l * (N_ROWS / 8);
        if (l == 0)
            vq_gather_kernel<true, false><<<N_ROWS / 8, 256>>>(
                El, p_resid, p_residb, p_codesum, p_csb, p_arg + l * N_ROWS, vp);
        else if (l == HQ - 1)
            vq_gather_kernel<false, true><<<N_ROWS / 8, 256>>>(
                El, p_resid, p_residb, p_codesum, p_csb, p_arg + l * N_ROWS, vp);
        else
            vq_gather_kernel<false, false><<<N_ROWS / 8, 256>>>(
                El, p_resid, p_residb, p_codesum, p_csb, p_arg + l * N_ROWS, vp);
    }

    // decoder (g_hb reused as dh bf16)
    tc_gemm<EPI_RELU><<<dim3(HID / TILE_N, N_ROWS / TILE_M), 256, DYN_SMEM>>>(
        p_csb, p_dw1t, LAT, db1, nullptr, p_hb, nullptr, nullptr);
    tc_gemm<EPI_MSE><<<dim3(OBS / TILE_N, N_ROWS / TILE_M), 256, DYN_SMEM>>>(
        p_hb, p_dw2t, HID, db2, nullptr, nullptr, x, p_rp);

    final_kernel<<<1, 256>>>(p_vqp, p_rp, out);
}

// round 14
// speedup vs baseline: 1.0159x; 1.0103x over previous
#include <cuda_runtime.h>
#include <cuda_bf16.h>
#include <cstdint>

#define N_ROWS 16384
#define OBS    1024
#define HID    2048
#define LAT    256
#define VOCAB  8192
#define HQ     4
#define LN_EPS 1e-5f

// ---------------- tiling ----------------
#define TILE_M 128
#define TILE_N 128
#define TILE_K 64
#define NSTAGE 3
#define STAGE_BYTES (TILE_M*128 + TILE_N*128)
#define SMEM_AUX 0
#define SMEM_STAGE0 1024
#define DYN_SMEM (SMEM_STAGE0 + NSTAGE*STAGE_BYTES)
#define A_STAGE_OFF(s) (SMEM_STAGE0 + (s)*STAGE_BYTES)
#define B_STAGE_OFF(s) (A_STAGE_OFF(s) + TILE_M*128)

enum { EPI_H = 0, EPI_LAT = 1, EPI_RELU = 3, EPI_MSE = 4 };

// ---------------- dist kernel layout (A-resident, 4 n-tiles per CTA) ----------------
#define DSLICES 16                  // n-slices; 64 n-tiles / 16 = 4 per CTA
#define DNT 4                       // n-tiles per CTA
#define DS_ENORM 0                  // 2 KB (512 floats)
#define DS_A     2048               // 64 KB: 4 K-chunks x 16 KB
#define DS_B     (2048 + 65536)     // 2 stages x 16 KB
#define DK_SMEM  (2048 + 65536 + 32768)   // 100352

// ---------------- scratch ----------------
__device__ __align__(1024) __nv_bfloat16 g_xb[(size_t)N_ROWS * OBS];
__device__ __align__(1024) __nv_bfloat16 g_hb[(size_t)N_ROWS * HID];
__device__ __align__(1024) __nv_bfloat16 g_residb[(size_t)N_ROWS * LAT];
__device__ __align__(1024) __nv_bfloat16 g_csb[(size_t)N_ROWS * LAT];
__device__ __align__(1024) __nv_bfloat16 g_cbb[(size_t)HQ * VOCAB * LAT];
__device__ __align__(1024) __nv_bfloat16 g_w1t[(size_t)HID * OBS];
__device__ __align__(1024) __nv_bfloat16 g_w2t[(size_t)LAT * HID];
__device__ __align__(1024) __nv_bfloat16 g_dw1t[(size_t)HID * LAT];
__device__ __align__(1024) __nv_bfloat16 g_dw2t[(size_t)OBS * HID];
__device__ float g_resid[(size_t)N_ROWS * LAT];
__device__ float g_codesum[(size_t)N_ROWS * LAT];
__device__ float g_enorm[HQ * VOCAB];
__device__ unsigned long long g_argmin[HQ * N_ROWS];
__device__ float g_vq_partials[HQ * (N_ROWS / 8)];
#define RP_COUNT ((N_ROWS / TILE_M) * (OBS / TILE_N))
__device__ float g_recon_partials[RP_COUNT];

// ---------------- helpers ----------------
__device__ __forceinline__ uint32_t smem_u32(const void* p) {
    uint32_t a;
    asm("{ .reg .u64 t; cvta.to.shared.u64 t, %1; cvt.u32.u64 %0, t; }" : "=r"(a) : "l"(p));
    return a;
}
#define SWZ(o) ((o) ^ (((o) >> 3) & 0x70))
#define CP_ASYNC16(dst, src) \
    asm volatile("cp.async.cg.shared.global [%0], [%1], 16;" :: "r"((uint32_t)(dst)), "l"(src))
#define CP_COMMIT() asm volatile("cp.async.commit_group;" ::: "memory")

__device__ __forceinline__ void ldsm_x4(uint32_t addr, uint32_t& r0, uint32_t& r1,
                                        uint32_t& r2, uint32_t& r3) {
    asm volatile("ldmatrix.sync.aligned.m8n8.x4.shared.b16 {%0,%1,%2,%3}, [%4];"
                 : "=r"(r0), "=r"(r1), "=r"(r2), "=r"(r3) : "r"(addr));
}
__device__ __forceinline__ void mma_bf16(float* d, uint32_t a0, uint32_t a1,
                                         uint32_t a2, uint32_t a3,
                                         uint32_t b0, uint32_t b1) {
    asm volatile("mma.sync.aligned.m16n8k16.row.col.f32.bf16.bf16.f32 "
                 "{%0,%1,%2,%3}, {%4,%5,%6,%7}, {%8,%9}, {%0,%1,%2,%3};"
                 : "+f"(d[0]), "+f"(d[1]), "+f"(d[2]), "+f"(d[3])
                 : "r"(a0), "r"(a1), "r"(a2), "r"(a3), "r"(b0), "r"(b1));
}
__device__ __forceinline__ unsigned f2ord(float f) {
    unsigned u = __float_as_uint(f);
    return (u & 0x80000000u) ? ~u : (u | 0x80000000u);
}

// fill one generic pipeline stage
__device__ __forceinline__ void fill_stage(
    uint32_t smem_base, int s, const __nv_bfloat16* __restrict__ A,
    const __nv_bfloat16* __restrict__ B, int K, int m0, int n0, int chunk, int tid)
{
    const int kt = chunk * TILE_K;
    const uint32_t a_s = smem_base + A_STAGE_OFF(s);
    const uint32_t b_s = smem_base + B_STAGE_OFF(s);
#pragma unroll
    for (int i = 0; i < 4; i++) {
        const int c = tid + i * 256;
        const int row = c >> 3;
        const int o = (c & 7) * 16;
        CP_ASYNC16(a_s + SWZ(row * 128 + o),
                   (const char*)(A + (size_t)(m0 + row) * K + kt) + o);
    }
#pragma unroll
    for (int i = 0; i < 4; i++) {
        const int c = tid + i * 256;
        const int row = c >> 3;
        const int o = (c & 7) * 16;
        CP_ASYNC16(b_s + SWZ(row * 128 + o),
                   (const char*)(B + (size_t)(n0 + row) * K + kt) + o);
    }
}

// ---------------- bf16 mma.sync GEMM with fused epilogues (enc/dec) ----------------
template<int EPI>
__global__ void __launch_bounds__(256, 2) tc_gemm(
    const __nv_bfloat16* __restrict__ A, const __nv_bfloat16* __restrict__ B, int K,
    const float* __restrict__ aux_vec,
    float* __restrict__ out_f32,
    __nv_bfloat16* __restrict__ out_bf16,
    const float* __restrict__ xref,
    float* __restrict__ partials)
{
    extern __shared__ __align__(1024) char smem[];
    const uint32_t smem_base = smem_u32(smem);
    const int tid = threadIdx.x;
    const int lane = tid & 31, wid = tid >> 5;
    const int wm = wid >> 1, wn = wid & 1;
    const int m0 = blockIdx.y * TILE_M;
    const int n0 = blockIdx.x * TILE_N;
    const int Nn = gridDim.x * TILE_N;
    const int niter = K >> 6;

    float* aux = (float*)(smem + SMEM_AUX);
    if (tid < 128) aux[tid] = aux_vec[n0 + tid];

    float acc[2][8][4];
#pragma unroll
    for (int fi = 0; fi < 2; fi++)
#pragma unroll
        for (int nf = 0; nf < 8; nf++)
#pragma unroll
            for (int q = 0; q < 4; q++) acc[fi][nf][q] = 0.f;

    const int a_row_l = wm * 32 + (lane & 15);
    const int a_kb_l  = (lane >> 4) * 16;
    const int b_row_l = wn * 64 + (lane & 7) + ((lane >> 4) & 1) * 8;
    const int b_kb_l  = (lane & 8) ? 16 : 0;

    fill_stage(smem_base, 0, A, B, K, m0, n0, 0, tid); CP_COMMIT();
    fill_stage(smem_base, 1, A, B, K, m0, n0, 1, tid); CP_COMMIT();

    int s = 0;
    for (int it = 0; it < niter; ++it) {
        if (it < niter - 1) { asm volatile("cp.async.wait_group 1;" ::: "memory"); }
        else                { asm volatile("cp.async.wait_group 0;" ::: "memory"); }
        __syncthreads();

        if (it + 2 < niter) {
            int fs = s + 2; if (fs >= NSTAGE) fs -= NSTAGE;
            fill_stage(smem_base, fs, A, B, K, m0, n0, it + 2, tid);
            CP_COMMIT();
        }

        const uint32_t a_s = smem_base + A_STAGE_OFF(s);
        const uint32_t b_s = smem_base + B_STAGE_OFF(s);
#pragma unroll
        for (int k = 0; k < 4; ++k) {
            const int kb = k * 32;
            uint32_t a[2][4];
#pragma unroll
            for (int fi = 0; fi < 2; fi++) {
                const int row = a_row_l + fi * 16;
                ldsm_x4(a_s + SWZ(row * 128 + kb + a_kb_l),
                        a[fi][0], a[fi][1], a[fi][2], a[fi][3]);
            }
            uint32_t b[8][2];
#pragma unroll
            for (int nf2 = 0; nf2 < 4; nf2++) {
                const int row = b_row_l + nf2 * 16;
                ldsm_x4(b_s + SWZ(row * 128 + kb + b_kb_l),
                        b[nf2*2][0], b[nf2*2][1], b[nf2*2+1][0], b[nf2*2+1][1]);
            }
#pragma unroll
            for (int fi = 0; fi < 2; fi++)
#pragma unroll
                for (int nf = 0; nf < 8; nf++)
                    mma_bf16(acc[fi][nf], a[fi][0], a[fi][1], a[fi][2], a[fi][3],
                             b[nf][0], b[nf][1]);
        }
        if (++s >= NSTAGE) s = 0;
    }

    const int tr = lane >> 2;
    const int tc = (lane & 3) * 2;

    if (EPI == EPI_MSE) {
        float ls = 0.f;
#pragma unroll
        for (int fi = 0; fi < 2; fi++)
#pragma unroll
            for (int half = 0; half < 2; half++) {
                const size_t row = (size_t)(m0 + wm * 32 + fi * 16 + tr + half * 8);
#pragma unroll
                for (int nf = 0; nf < 8; nf++) {
                    const int col = wn * 64 + nf * 8 + tc;
                    const float2 xv = *(const float2*)&xref[row * OBS + n0 + col];
                    float e0 = acc[fi][nf][half*2+0] + aux[col]   - xv.x;
                    float e1 = acc[fi][nf][half*2+1] + aux[col+1] - xv.y;
                    ls = fmaf(e0, e0, ls);
                    ls = fmaf(e1, e1, ls);
                }
            }
        __syncthreads();
        float* red = (float*)(smem + SMEM_STAGE0);
        red[tid] = ls;
        __syncthreads();
#pragma unroll
        for (int st = 128; st > 0; st >>= 1) {
            if (tid < st) red[tid] += red[tid + st];
            __syncthreads();
        }
        if (tid == 0) partials[blockIdx.y * gridDim.x + blockIdx.x] = red[0];
    } else {
#pragma unroll
        for (int fi = 0; fi < 2; fi++)
#pragma unroll
            for (int half = 0; half < 2; half++) {
                const size_t row = (size_t)(m0 + wm * 32 + fi * 16 + tr + half * 8);
#pragma unroll
                for (int nf = 0; nf < 8; nf++) {
                    const int col = wn * 64 + nf * 8 + tc;
                    float v0 = acc[fi][nf][half*2+0] + aux[col];
                    float v1 = acc[fi][nf][half*2+1] + aux[col+1];
                    if (EPI == EPI_RELU) { v0 = fmaxf(v0, 0.f); v1 = fmaxf(v1, 0.f); }
                    if (EPI == EPI_LAT)
                        *(float2*)&out_f32[row * Nn + n0 + col] = make_float2(v0, v1);
                    __nv_bfloat162 p = __float22bfloat162_rn(make_float2(v0, v1));
                    *(__nv_bfloat162*)&out_bf16[row * Nn + n0 + col] = p;
                }
            }
    }
}

// ---------------- A-resident distance/argmin kernel ----------------
// grid (DSLICES, N_ROWS/128); each CTA: 128 rows resident, DNT n-tiles streamed.
__device__ __forceinline__ void dist_fill_b(
    uint32_t base, int stage, const __nv_bfloat16* __restrict__ B,
    int n0, int kc, int tid)
{
    const uint32_t b_s = base + DS_B + stage * 16384;
#pragma unroll
    for (int i = 0; i < 4; i++) {
        const int c = tid + i * 256;
        const int row = c >> 3;
        const int o = (c & 7) * 16;
        CP_ASYNC16(b_s + SWZ(row * 128 + o),
                   (const char*)(B + (size_t)(n0 + row) * 256) + kc * 128 + o);
    }
}

__global__ void __launch_bounds__(256, 2) dist_kernel(
    const __nv_bfloat16* __restrict__ A,   // resid bf16 [N_ROWS, 256]
    const __nv_bfloat16* __restrict__ B,   // codebook level bf16 [VOCAB, 256]
    const float* __restrict__ enorm,
    unsigned long long* __restrict__ argmin)
{
    extern __shared__ __align__(1024) char smem[];
    const uint32_t base = smem_u32(smem);
    const int tid = threadIdx.x;
    const int lane = tid & 31, wid = tid >> 5;
    const int wm = wid >> 1, wn = wid & 1;
    const int m0 = blockIdx.y * 128;
    const int nbase = blockIdx.x * (DNT * 128);

    // enorm slice (DNT*128 = 512 floats)
    float* esm = (float*)(smem + DS_ENORM);
    if (tid < 128) ((float4*)esm)[tid] = ((const float4*)(enorm + nbase))[tid];

    // A resident: 4 K-chunks x [128 rows x 128B], each chunk swizzled independently
#pragma unroll
    for (int i = 0; i < 16; i++) {
        const int c = tid + i * 256;          // 0..4095 (16B units)
        const int chunk = c >> 10;
        const int u = c & 1023;
        const int row = u >> 3;
        const int o = (u & 7) * 16;
        CP_ASYNC16(base + DS_A + chunk * 16384 + SWZ(row * 128 + o),
                   (const char*)(A + (size_t)(m0 + row) * 256) + chunk * 128 + o);
    }
    CP_COMMIT();
    dist_fill_b(base, 0, B, nbase, 0, tid); CP_COMMIT();
    dist_fill_b(base, 1, B, nbase, 1, tid); CP_COMMIT();

    float acc[2][8][4];
#pragma unroll
    for (int fi = 0; fi < 2; fi++)
#pragma unroll
        for (int nf = 0; nf < 8; nf++)
#pragma unroll
            for (int q = 0; q < 4; q++) acc[fi][nf][q] = 0.f;

    float best[2][2];
    int bi[2][2];
#pragma unroll
    for (int fi = 0; fi < 2; fi++)
#pragma unroll
        for (int hf = 0; hf < 2; hf++) { best[fi][hf] = __int_as_float(0x7f800000); bi[fi][hf] = 0; }

    const int a_row_l = wm * 32 + (lane & 15);
    const int a_kb_l  = (lane >> 4) * 16;
    const int b_row_l = wn * 64 + (lane & 7) + ((lane >> 4) & 1) * 8;
    const int b_kb_l  = (lane & 8) ? 16 : 0;
    const int tc = (lane & 3) * 2;

    const int NIT = DNT * 4;
    for (int g = 0; g < NIT; ++g) {
        if (g < NIT - 1) { asm volatile("cp.async.wait_group 1;" ::: "memory"); }
        else             { asm volatile("cp.async.wait_group 0;" ::: "memory"); }
        __syncthreads();

        const int kc = g & 3;
        const uint32_t a_s = base + DS_A + kc * 16384;
        const uint32_t b_s = base + DS_B + (g & 1) * 16384;
#pragma unroll
        for (int k = 0; k < 4; ++k) {
            const int kb = k * 32;
            uint32_t a[2][4];
#pragma unroll
            for (int fi = 0; fi < 2; fi++) {
                const int row = a_row_l + fi * 16;
                ldsm_x4(a_s + SWZ(row * 128 + kb + a_kb_l),
                        a[fi][0], a[fi][1], a[fi][2], a[fi][3]);
            }
            uint32_t b[8][2];
#pragma unroll
            for (int nf2 = 0; nf2 < 4; nf2++) {
                const int row = b_row_l + nf2 * 16;
                ldsm_x4(b_s + SWZ(row * 128 + kb + b_kb_l),
                        b[nf2*2][0], b[nf2*2][1], b[nf2*2+1][0], b[nf2*2+1][1]);
            }
#pragma unroll
            for (int fi = 0; fi < 2; fi++)
#pragma unroll
                for (int nf = 0; nf < 8; nf++)
                    mma_bf16(acc[fi][nf], a[fi][0], a[fi][1], a[fi][2], a[fi][3],
                             b[nf][0], b[nf][1]);
        }

        if (kc == 3) {
            // n-tile complete: fold into running argmin, reset acc
            const int lt = (g >> 2) * 128;          // local col base within slice
#pragma unroll
            for (int fi = 0; fi < 2; fi++)
#pragma unroll
                for (int hf = 0; hf < 2; hf++) {
                    float bst = best[fi][hf];
                    int bidx = bi[fi][hf];
#pragma unroll
                    for (int nf = 0; nf < 8; nf++) {
                        const int lc = lt + wn * 64 + nf * 8 + tc;
                        const float d0 = fmaf(-2.f, acc[fi][nf][hf*2+0], esm[lc]);
                        const float d1 = fmaf(-2.f, acc[fi][nf][hf*2+1], esm[lc+1]);
                        if (d0 < bst) { bst = d0; bidx = nbase + lc; }
                        if (d1 < bst) { bst = d1; bidx = nbase + lc + 1; }
                    }
                    best[fi][hf] = bst;
                    bi[fi][hf] = bidx;
                }
#pragma unroll
            for (int fi = 0; fi < 2; fi++)
#pragma unroll
                for (int nf = 0; nf < 8; nf++)
#pragma unroll
                    for (int q = 0; q < 4; q++) acc[fi][nf][q] = 0.f;
        }

        __syncthreads();     // all warps done reading stage (g&1) before refill
        if (g + 2 < NIT) {
            const int gn = g + 2;
            dist_fill_b(base, g & 1, B, nbase + (gn >> 2) * 128, gn & 3, tid);
            CP_COMMIT();
        }
    }

    // final: quad-reduce and one atomicMin per row
    const int tr = lane >> 2;
#pragma unroll
    for (int fi = 0; fi < 2; fi++)
#pragma unroll
        for (int hf = 0; hf < 2; hf++) {
            unsigned long long key =
                ((unsigned long long)f2ord(best[fi][hf]) << 32) | (unsigned)bi[fi][hf];
            unsigned long long o;
            o = __shfl_xor_sync(0xffffffffu, key, 1); if (o < key) key = o;
            o = __shfl_xor_sync(0xffffffffu, key, 2); if (o < key) key = o;
            if ((lane & 3) == 0) {
                const int row = m0 + wm * 32 + fi * 16 + tr + hf * 8;
                atomicMin(&argmin[row], key);
            }
        }
}

// ---------------- fused prep: x->bf16, cb->bf16+enorm, argmin init, transposes ----------------
#define PREP_XB   16384
#define PREP_CB   4096
#define PREP_ARG  256
#define PREP_TR1  2048
#define PREP_TR2  512
#define PREP_TR3  512
#define PREP_TR4  2048
#define PREP_GRID (PREP_XB + PREP_CB + PREP_ARG + PREP_TR1 + PREP_TR2 + PREP_TR3 + PREP_TR4)

__global__ void __launch_bounds__(256) prep_kernel(
    const float* __restrict__ x, const float* __restrict__ cb,
    const float* __restrict__ ew1, const float* __restrict__ ew2,
    const float* __restrict__ dw1, const float* __restrict__ dw2,
    __nv_bfloat16* __restrict__ xb, __nv_bfloat16* __restrict__ cbb,
    float* __restrict__ en, unsigned long long* __restrict__ arg,
    __nv_bfloat16* __restrict__ w1t, __nv_bfloat16* __restrict__ w2t,
    __nv_bfloat16* __restrict__ dw1t, __nv_bfloat16* __restrict__ dw2t)
{
    __shared__ float tsm[32][33];
    const int b = blockIdx.x;
    const int tid = threadIdx.x;
    if (b < PREP_XB) {
        const size_t i = (size_t)b * 256 + tid;
        const float4 v = ((const float4*)x)[i];
        ((__nv_bfloat162*)xb)[2 * i + 0] = __float22bfloat162_rn(make_float2(v.x, v.y));
        ((__nv_bfloat162*)xb)[2 * i + 1] = __float22bfloat162_rn(make_float2(v.z, v.w));
    } else if (b < PREP_XB + PREP_CB) {
        const int row = (b - PREP_XB) * 8 + (tid >> 5);
        const int lane = tid & 31;
        float s = 0.f;
#pragma unroll
        for (int h = 0; h < 2; h++) {
            const float4 v = ((const float4*)cb)[(size_t)row * 64 + h * 32 + lane];
            s = fmaf(v.x, v.x, s); s = fmaf(v.y, v.y, s);
            s = fmaf(v.z, v.z, s); s = fmaf(v.w, v.w, s);
            uint2 p;
            __nv_bfloat162 p0 = __float22bfloat162_rn(make_float2(v.x, v.y));
            __nv_bfloat162 p1 = __float22bfloat162_rn(make_float2(v.z, v.w));
            p.x = *(uint32_t*)&p0; p.y = *(uint32_t*)&p1;
            ((uint2*)cbb)[(size_t)row * 64 + h * 32 + lane] = p;
        }
#pragma unroll
        for (int off = 16; off > 0; off >>= 1) s += __shfl_down_sync(0xffffffffu, s, off);
        if (lane == 0) en[row] = s;
    } else if (b < PREP_XB + PREP_CB + PREP_ARG) {
        const int ab = b - PREP_XB - PREP_CB;
        arg[(size_t)ab * 256 + tid] = ~0ull;
    } else {
        int t = b - PREP_XB - PREP_CB - PREP_ARG;
        const float* in; __nv_bfloat16* outp; int R, C;
        if (t < PREP_TR1)                 { in = ew1; outp = w1t;  R = OBS; C = HID; }
        else if (t < PREP_TR1 + PREP_TR2) { t -= PREP_TR1; in = ew2; outp = w2t;  R = HID; C = LAT; }
        else if (t < PREP_TR1 + PREP_TR2 + PREP_TR3)
                                          { t -= PREP_TR1 + PREP_TR2; in = dw1; outp = dw1t; R = LAT; C = HID; }
        else                              { t -= PREP_TR1 + PREP_TR2 + PREP_TR3; in = dw2; outp = dw2t; R = HID; C = OBS; }
        const int cw = C / 32;
        const int c0 = (t % cw) * 32, r0 = (t / cw) * 32;
        const int tx = tid & 31, ty = tid >> 5;
#pragma unroll
        for (int i = 0; i < 32; i += 8)
            tsm[ty + i][tx] = in[(size_t)(r0 + ty + i) * C + c0 + tx];
        __syncthreads();
#pragma unroll
        for (int i = 0; i < 32; i += 8)
            outp[(size_t)(c0 + ty + i) * R + r0 + tx] = __float2bfloat16_rn(tsm[tx][ty + i]);
    }
}

// ---------------- LayerNorm + ReLU on bf16 in place (uint4 I/O) ----------------
__global__ void __launch_bounds__(256) ln_relu_kernel(
    __nv_bfloat16* __restrict__ h, const float* __restrict__ g, const float* __restrict__ b)
{
    const int row = blockIdx.x;
    uint4* hr = (uint4*)(h + (size_t)row * HID);
    const uint4 v = hr[threadIdx.x];
    float f[8];
    {
        const __nv_bfloat162* p = (const __nv_bfloat162*)&v;
#pragma unroll
        for (int i = 0; i < 4; i++) {
            f[2 * i]     = __bfloat162float(p[i].x);
            f[2 * i + 1] = __bfloat162float(p[i].y);
        }
    }
    float s = 0.f, s2 = 0.f;
#pragma unroll
    for (int i = 0; i < 8; i++) { s += f[i]; s2 = fmaf(f[i], f[i], s2); }

    __shared__ float sh1[256], sh2[256];
    sh1[threadIdx.x] = s; sh2[threadIdx.x] = s2;
    __syncthreads();
    for (int st = 128; st > 0; st >>= 1) {
        if (threadIdx.x < st) {
            sh1[threadIdx.x] += sh1[threadIdx.x + st];
            sh2[threadIdx.x] += sh2[threadIdx.x + st];
        }
        __syncthreads();
    }
    const float mu  = sh1[0] * (1.f / HID);
    const float var = sh2[0] * (1.f / HID) - mu * mu;
    const float inv = rsqrtf(var + LN_EPS);

    const float4 g0 = ((const float4*)g)[threadIdx.x * 2];
    const float4 g1 = ((const float4*)g)[threadIdx.x * 2 + 1];
    const float4 b0 = ((const float4*)b)[threadIdx.x * 2];
    const float4 b1 = ((const float4*)b)[threadIdx.x * 2 + 1];
    const float gg[8] = {g0.x, g0.y, g0.z, g0.w, g1.x, g1.y, g1.z, g1.w};
    const float bb[8] = {b0.x, b0.y, b0.z, b0.w, b1.x, b1.y, b1.z, b1.w};

    uint4 o;
    __nv_bfloat162* po = (__nv_bfloat162*)&o;
#pragma unroll
    for (int i = 0; i < 4; i++) {
        const float v0 = fmaxf((f[2*i]   - mu) * inv * gg[2*i]   + bb[2*i],   0.f);
        const float v1 = fmaxf((f[2*i+1] - mu) * inv * gg[2*i+1] + bb[2*i+1], 0.f);
        po[i] = __float22bfloat162_rn(make_float2(v0, v1));
    }
    hr[threadIdx.x] = o;
}

// ---------------- VQ gather + loss partial + resid/codesum update ----------------
template<bool FIRST, bool LAST>
__global__ void __launch_bounds__(256) vq_gather_kernel(
    const float* __restrict__ E, float* __restrict__ resid,
    __nv_bfloat16* __restrict__ residb,
    float* __restrict__ codesum, __nv_bfloat16* __restrict__ csb,
    const unsigned long long* __restrict__ argmin, float* __restrict__ partials)
{
    const int warp = threadIdx.x >> 5;
    const int lane = threadIdx.x & 31;
    const int row  = blockIdx.x * 8 + warp;
    const unsigned idx = (unsigned)(argmin[row] & 0xffffffffu);
    const float* q = E + (size_t)idx * LAT;
    float* rr = resid   + (size_t)row * LAT;
    float* cs = codesum + (size_t)row * LAT;
    __nv_bfloat16* rb = residb + (size_t)row * LAT;
    __nv_bfloat16* cbp = csb   + (size_t)row * LAT;
    float lsum = 0.f;
#pragma unroll
    for (int c = lane * 4; c < LAT; c += 128) {
        const float4 qv = *(const float4*)&q[c];
        const float4 rv = *(const float4*)&rr[c];
        const float dx = qv.x - rv.x, dy = qv.y - rv.y;
        const float dz = qv.z - rv.z, dw = qv.w - rv.w;
        lsum += dx * dx + dy * dy + dz * dz + dw * dw;
        const float4 nr = make_float4(rv.x - qv.x, rv.y - qv.y, rv.z - qv.z, rv.w - qv.w);
        *(float4*)&rr[c] = nr;
        float4 cv;
        if (FIRST) cv = qv;
        else {
            cv = *(float4*)&cs[c];
            cv.x += qv.x; cv.y += qv.y; cv.z += qv.z; cv.w += qv.w;
        }
        *(float4*)&cs[c] = cv;
        if (LAST) {
            ((__nv_bfloat162*)&cbp[c])[0] = __float22bfloat162_rn(make_float2(cv.x, cv.y));
            ((__nv_bfloat162*)&cbp[c])[1] = __float22bfloat162_rn(make_float2(cv.z, cv.w));
        } else {
            ((__nv_bfloat162*)&rb[c])[0] = __float22bfloat162_rn(make_float2(nr.x, nr.y));
            ((__nv_bfloat162*)&rb[c])[1] = __float22bfloat162_rn(make_float2(nr.z, nr.w));
        }
    }
#pragma unroll
    for (int off = 16; off > 0; off >>= 1) lsum += __shfl_down_sync(0xffffffffu, lsum, off);
    __shared__ float ws[8];
    if (lane == 0) ws[warp] = lsum;
    __syncthreads();
    if (threadIdx.x == 0) {
        float t = 0.f;
#pragma unroll
        for (int w = 0; w < 8; w++) t += ws[w];
        partials[blockIdx.x] = t;
    }
}

// ---------------- final deterministic reduction ----------------
__global__ void __launch_bounds__(256) final_kernel(
    const float* __restrict__ vqp, const float* __restrict__ rp, float* __restrict__ out)
{
    __shared__ float sv[256], sr[256];
    float a = 0.f, b = 0.f;
    for (int i = threadIdx.x; i < HQ * (N_ROWS / 8); i += 256) a += vqp[i];
    for (int i = threadIdx.x; i < RP_COUNT; i += 256) b += rp[i];
    sv[threadIdx.x] = a; sr[threadIdx.x] = b;
    __syncthreads();
    for (int s = 128; s > 0; s >>= 1) {
        if (threadIdx.x < s) {
            sv[threadIdx.x] += sv[threadIdx.x + s];
            sr[threadIdx.x] += sr[threadIdx.x + s];
        }
        __syncthreads();
    }
    if (threadIdx.x == 0) {
        out[0] = 1.5f * sv[0] / ((float)N_ROWS * (float)LAT)
               + 0.5f * sr[0] / ((float)N_ROWS * (float)OBS);
    }
}

// ---------------- host launcher ----------------
extern "C" void kernel_launch(void* const* d_in, const int* in_sizes, int n_in,
                              void* d_out, int out_size)
{
    const float* x   = (const float*)d_in[0];
    const float* cb  = (const float*)d_in[1];
    const float* ew1 = (const float*)d_in[2];
    const float* eb1 = (const float*)d_in[3];
    const float* lng = (const float*)d_in[4];
    const float* lnb = (const float*)d_in[5];
    const float* ew2 = (const float*)d_in[6];
    const float* eb2 = (const float*)d_in[7];
    const float* dw1 = (const float*)d_in[8];
    const float* db1 = (const float*)d_in[9];
    const float* dw2 = (const float*)d_in[10];
    const float* db2 = (const float*)d_in[11];
    float* out = (float*)d_out;

    float *p_resid, *p_codesum, *p_enorm, *p_vqp, *p_rp;
    unsigned long long* p_arg;
    __nv_bfloat16 *p_xb, *p_hb, *p_residb, *p_csb, *p_cbb, *p_w1t, *p_w2t, *p_dw1t, *p_dw2t;
    cudaGetSymbolAddress((void**)&p_resid,   g_resid);
    cudaGetSymbolAddress((void**)&p_codesum, g_codesum);
    cudaGetSymbolAddress((void**)&p_enorm,   g_enorm);
    cudaGetSymbolAddress((void**)&p_arg,     g_argmin);
    cudaGetSymbolAddress((void**)&p_vqp,     g_vq_partials);
    cudaGetSymbolAddress((void**)&p_rp,      g_recon_partials);
    cudaGetSymbolAddress((void**)&p_xb,      g_xb);
    cudaGetSymbolAddress((void**)&p_hb,      g_hb);
    cudaGetSymbolAddress((void**)&p_residb,  g_residb);
    cudaGetSymbolAddress((void**)&p_csb,     g_csb);
    cudaGetSymbolAddress((void**)&p_cbb,     g_cbb);
    cudaGetSymbolAddress((void**)&p_w1t,     g_w1t);
    cudaGetSymbolAddress((void**)&p_w2t,     g_w2t);
    cudaGetSymbolAddress((void**)&p_dw1t,    g_dw1t);
    cudaGetSymbolAddress((void**)&p_dw2t,    g_dw2t);

    cudaFuncSetAttribute(tc_gemm<EPI_H>,    cudaFuncAttributeMaxDynamicSharedMemorySize, DYN_SMEM);
    cudaFuncSetAttribute(tc_gemm<EPI_LAT>,  cudaFuncAttributeMaxDynamicSharedMemorySize, DYN_SMEM);
    cudaFuncSetAttribute(tc_gemm<EPI_RELU>, cudaFuncAttributeMaxDynamicSharedMemorySize, DYN_SMEM);
    cudaFuncSetAttribute(tc_gemm<EPI_MSE>,  cudaFuncAttributeMaxDynamicSharedMemorySize, DYN_SMEM);
    cudaFuncSetAttribute(dist_kernel,       cudaFuncAttributeMaxDynamicSharedMemorySize, DK_SMEM);

    // 1: fused prep (x->bf16, cb->bf16+enorm, argmin init, all transposes)
    prep_kernel<<<PREP_GRID, 256>>>(x, cb, ew1, ew2, dw1, dw2,
                                    p_xb, p_cbb, p_enorm, p_arg,
                                    p_w1t, p_w2t, p_dw1t, p_dw2t);
    // 2: encoder GEMM1 -> bf16 h
    tc_gemm<EPI_H><<<dim3(HID / TILE_N, N_ROWS / TILE_M), 256, DYN_SMEM>>>(
        p_xb, p_w1t, OBS, eb1, nullptr, p_hb, nullptr, nullptr);
    // 3: LN+ReLU in place on bf16
    ln_relu_kernel<<<N_ROWS, 256>>>(p_hb, lng, lnb);
    // 4: encoder GEMM2 -> resid f32 + bf16
    tc_gemm<EPI_LAT><<<dim3(LAT / TILE_N, N_ROWS / TILE_M), 256, DYN_SMEM>>>(
        p_hb, p_w2t, HID, eb2, p_resid, p_residb, nullptr, nullptr);

    // residual VQ levels (A-resident dist kernel, 4 n-tiles per CTA)
    for (int l = 0; l < HQ; ++l) {
        dist_kernel<<<dim3(DSLICES, N_ROWS / 128), 256, DK_SMEM>>>(
            p_residb, p_cbb + (size_t)l * VOCAB * LAT,
            p_enorm + l * VOCAB, p_arg + l * N_ROWS);
        const float* El = cb + (size_t)l * VOCAB * LAT;
        float* vp = p_vqp + l * (N_ROWS / 8);
        if (l == 0)
            vq_gather_kernel<true, false><<<N_ROWS / 8, 256>>>(
                El, p_resid, p_residb, p_codesum, p_csb, p_arg + l * N_ROWS, vp);
        else if (l == HQ - 1)
            vq_gather_kernel<false, true><<<N_ROWS / 8, 256>>>(
                El, p_resid, p_residb, p_codesum, p_csb, p_arg + l * N_ROWS, vp);
        else
            vq_gather_kernel<false, false><<<N_ROWS / 8, 256>>>(
                El, p_resid, p_residb, p_codesum, p_csb, p_arg + l * N_ROWS, vp);
    }

    // decoder (g_hb reused as dh bf16)
    tc_gemm<EPI_RELU><<<dim3(HID / TILE_N, N_ROWS / TILE_M), 256, DYN_SMEM>>>(
        p_csb, p_dw1t, LAT, db1, nullptr, p_hb, nullptr, nullptr);
    tc_gemm<EPI_MSE><<<dim3(OBS / TILE_N, N_ROWS / TILE_M), 256, DYN_SMEM>>>(
        p_hb, p_dw2t, HID, db2, nullptr, nullptr, x, p_rp);

    final_kernel<<<1, 256>>>(p_vqp, p_rp, out);
}